// round 3
// baseline (speedup 1.0000x reference)
#include <cuda_runtime.h>
#include <math.h>

#define B_ 4
#define D_ 12
#define L_ 512
#define H_ 768
#define F_ 4096
#define NHD_ 8
#define HD_ 96
#define TOPK_ 64
#define NROWS_ (B_*D_*L_)            /* 24576 */
#define BD_ (B_*D_)                  /* 48 */

// ---------------- static scratch (no allocations allowed) ----------------
__device__ float g_x  [NROWS_*H_];
__device__ float g_ln [NROWS_*H_];
__device__ float g_q  [NROWS_*H_];
__device__ float g_k  [NROWS_*H_];
__device__ float g_v  [NROWS_*H_];
__device__ float g_o  [NROWS_*H_];
__device__ float g_x1 [NROWS_*H_];
__device__ float g_big[100663296];   // scores (384*512*512) then z_dense (24576*4096)
__device__ float g_decT[F_*H_];      // transposed dictionary_dec
__device__ float g_off[F_];
__device__ double g_acc[3];          // [0]=sum(xprior-zL)^2  [1]=sum(xtgt-xsrc)^2  [2]=sum z

// ---------------- reductions ----------------
__device__ __forceinline__ float blockReduceSum(float v, float* sh) {
    int t = threadIdx.x, lane = t & 31, w = t >> 5, nw = blockDim.x >> 5;
    #pragma unroll
    for (int o = 16; o; o >>= 1) v += __shfl_down_sync(0xffffffffu, v, o);
    __syncthreads();
    if (lane == 0) sh[w] = v;
    __syncthreads();
    if (t == 0) { float s = 0.f; for (int i = 0; i < nw; i++) s += sh[i]; sh[32] = s; }
    __syncthreads();
    return sh[32];
}
__device__ __forceinline__ float blockReduceMax(float v, float* sh) {
    int t = threadIdx.x, lane = t & 31, w = t >> 5, nw = blockDim.x >> 5;
    #pragma unroll
    for (int o = 16; o; o >>= 1) v = fmaxf(v, __shfl_down_sync(0xffffffffu, v, o));
    __syncthreads();
    if (lane == 0) sh[w] = v;
    __syncthreads();
    if (t == 0) { float m = sh[0]; for (int i = 1; i < nw; i++) m = fmaxf(m, sh[i]); sh[32] = m; }
    __syncthreads();
    return sh[32];
}
__device__ __forceinline__ int blockReduceSumI(int v, int* sh) {
    int t = threadIdx.x, lane = t & 31, w = t >> 5, nw = blockDim.x >> 5;
    #pragma unroll
    for (int o = 16; o; o >>= 1) v += __shfl_down_sync(0xffffffffu, v, o);
    __syncthreads();
    if (lane == 0) sh[w] = v;
    __syncthreads();
    if (t == 0) { int s = 0; for (int i = 0; i < nw; i++) s += sh[i]; sh[32] = s; }
    __syncthreads();
    return sh[32];
}

// ---------------- misc ----------------
__global__ void zero_acc_kernel() {
    if (threadIdx.x < 3) g_acc[threadIdx.x] = 0.0;
}

// x = concat(query_token, zL[:, :-1]) along depth; g_ln = layer_norm(x, g_l, b_l)
__global__ void build_ln_kernel(const float* __restrict__ zL, const float* __restrict__ qtok,
                                const float* __restrict__ gw, const float* __restrict__ bw) {
    int row = blockIdx.x, t = threadIdx.x;
    int l = row % L_, d = (row / L_) % D_, b = row / (L_ * D_);
    const float* src = (d == 0) ? qtok
                                : (zL + ((long long)((b*D_ + (d-1))*L_ + l))*H_);
    float v0 = src[t], v1 = src[t+256], v2 = src[t+512];
    long long base = (long long)row * H_;
    g_x[base+t] = v0; g_x[base+t+256] = v1; g_x[base+t+512] = v2;
    __shared__ float sh[33];
    float mean = blockReduceSum(v0+v1+v2, sh) * (1.0f/H_);
    float d0 = v0-mean, d1 = v1-mean, d2 = v2-mean;
    float var = blockReduceSum(d0*d0+d1*d1+d2*d2, sh) * (1.0f/H_);
    float inv = rsqrtf(var + 1e-5f);
    g_ln[base+t]     = d0*inv*gw[t]     + bw[t];
    g_ln[base+t+256] = d1*inv*gw[t+256] + bw[t+256];
    g_ln[base+t+512] = d2*inv*gw[t+512] + bw[t+512];
}

// g_ln = layer_norm(g_x1, g_d, b_d)
__global__ void ln_d_kernel(const float* __restrict__ gw, const float* __restrict__ bw) {
    int row = blockIdx.x, t = threadIdx.x;
    long long base = (long long)row * H_;
    float v0 = g_x1[base+t], v1 = g_x1[base+t+256], v2 = g_x1[base+t+512];
    __shared__ float sh[33];
    float mean = blockReduceSum(v0+v1+v2, sh) * (1.0f/H_);
    float d0 = v0-mean, d1 = v1-mean, d2 = v2-mean;
    float var = blockReduceSum(d0*d0+d1*d1+d2*d2, sh) * (1.0f/H_);
    float inv = rsqrtf(var + 1e-5f);
    g_ln[base+t]     = d0*inv*gw[t]     + bw[t];
    g_ln[base+t+256] = d1*inv*gw[t+256] + bw[t+256];
    g_ln[base+t+512] = d2*inv*gw[t+512] + bw[t+512];
}

// ---------------- generic batched SGEMM ----------------
// TRANSB=1: C[m,n] = alpha*sum_k A[m,k]*B[n,k]    TRANSB=0: C[m,n] = alpha*sum_k A[m,k]*B[k,n]
// + optional bias[n] + res[m,n] + relu.  z-batched via bz=(z1,z2) strides. K mult of 8, N mult of 4.
template<int TRANSB>
__global__ void __launch_bounds__(256) gemm_kernel(
    const float* __restrict__ A, const float* __restrict__ Bm, float* __restrict__ C,
    int M, int Nn, int K, int lda, int ldb, int ldc,
    int zdiv,
    long long sA1, long long sA2, long long sB1, long long sB2,
    long long sC1, long long sC2,
    float alpha, const float* __restrict__ bias,
    const float* __restrict__ res, int ldres, int relu)
{
    __shared__ float As[8][128];
    __shared__ float Bs[8][128];
    int bz = blockIdx.z;
    int z1 = bz / zdiv, z2 = bz - z1 * zdiv;
    A  += z1*sA1 + z2*sA2;
    Bm += z1*sB1 + z2*sB2;
    C  += z1*sC1 + z2*sC2;
    int bm = blockIdx.y * 128, bn = blockIdx.x * 128;
    int t = threadIdx.x;
    int tx = t & 15, ty = t >> 4;
    float acc[8][8];
    #pragma unroll
    for (int i = 0; i < 8; i++)
        #pragma unroll
        for (int j = 0; j < 8; j++) acc[i][j] = 0.f;

    int mA = t >> 1, kA = (t & 1) * 4;
    for (int k0 = 0; k0 < K; k0 += 8) {
        {
            int gm = bm + mA;
            float4 va = make_float4(0.f,0.f,0.f,0.f);
            if (gm < M) va = *(const float4*)(A + (long long)gm*lda + (k0 + kA));
            As[kA+0][mA] = va.x; As[kA+1][mA] = va.y; As[kA+2][mA] = va.z; As[kA+3][mA] = va.w;
        }
        if (TRANSB) {
            int gn = bn + mA;
            float4 vb = make_float4(0.f,0.f,0.f,0.f);
            if (gn < Nn) vb = *(const float4*)(Bm + (long long)gn*ldb + (k0 + kA));
            Bs[kA+0][mA] = vb.x; Bs[kA+1][mA] = vb.y; Bs[kA+2][mA] = vb.z; Bs[kA+3][mA] = vb.w;
        } else {
            int kk = t >> 5, nb = (t & 31) * 4;
            int gn = bn + nb;
            const float* bp = Bm + (long long)(k0 + kk)*ldb;
            float4 vb = make_float4(0.f,0.f,0.f,0.f);
            if (gn + 3 < Nn) vb = *(const float4*)(bp + gn);
            *(float4*)&Bs[kk][nb] = vb;
        }
        __syncthreads();
        #pragma unroll
        for (int kk = 0; kk < 8; kk++) {
            float a[8], b[8];
            *(float4*)&a[0] = *(const float4*)&As[kk][ty*8];
            *(float4*)&a[4] = *(const float4*)&As[kk][ty*8+4];
            *(float4*)&b[0] = *(const float4*)&Bs[kk][tx*8];
            *(float4*)&b[4] = *(const float4*)&Bs[kk][tx*8+4];
            #pragma unroll
            for (int i = 0; i < 8; i++)
                #pragma unroll
                for (int j = 0; j < 8; j++)
                    acc[i][j] = fmaf(a[i], b[j], acc[i][j]);
        }
        __syncthreads();
    }
    #pragma unroll
    for (int i = 0; i < 8; i++) {
        int gm = bm + ty*8 + i;
        if (gm >= M) continue;
        long long crow = (long long)gm * ldc;
        #pragma unroll
        for (int j = 0; j < 8; j++) {
            int gn = bn + tx*8 + j;
            if (gn >= Nn) continue;
            float vv = acc[i][j] * alpha;
            if (bias) vv += bias[gn];
            if (res)  vv += res[(long long)gm*ldres + gn];
            if (relu) vv = fmaxf(vv, 0.f);
            C[crow + gn] = vv;
        }
    }
}

// ---------------- softmax over rows of 512 (L-attn scores, in place in g_big) ----------------
__global__ void softmax_kernel() {
    float* p = g_big + (long long)blockIdx.x * 512;
    int t = threadIdx.x; // 128
    float4 v = ((float4*)p)[t];
    __shared__ float sh[33];
    float m = blockReduceMax(fmaxf(fmaxf(v.x, v.y), fmaxf(v.z, v.w)), sh);
    v.x = expf(v.x - m); v.y = expf(v.y - m); v.z = expf(v.z - m); v.w = expf(v.w - m);
    float s = blockReduceSum(v.x + v.y + v.z + v.w, sh);
    float inv = 1.0f / s;
    v.x *= inv; v.y *= inv; v.z *= inv; v.w *= inv;
    ((float4*)p)[t] = v;
}

// ---------------- causal attention over D (seq len 12), per (b,l,h) ----------------
__global__ void dattn_kernel() {
    int bid = blockIdx.x;
    int h = bid % NHD_;
    int l = (bid / NHD_) % L_;
    int b = bid / (NHD_ * L_);
    __shared__ float sq[D_][HD_], sk[D_][HD_], sv[D_][HD_];
    __shared__ float sp[D_][D_];
    int t = threadIdx.x; // 128
    for (int idx = t; idx < D_*HD_; idx += 128) {
        int d = idx / HD_, c = idx - d*HD_;
        long long g = ((long long)((b*D_ + d)*L_ + l))*H_ + h*HD_ + c;
        sq[d][c] = g_q[g]; sk[d][c] = g_k[g]; sv[d][c] = g_v[g];
    }
    __syncthreads();
    const float scale = rsqrtf((float)HD_);
    for (int idx = t; idx < D_*D_; idx += 128) {
        int i = idx / D_, j = idx - i*D_;
        float s = 0.f;
        if (j <= i) {
            #pragma unroll 8
            for (int c = 0; c < HD_; c++) s = fmaf(sq[i][c], sk[j][c], s);
            s *= scale;
        }
        sp[i][j] = s;
    }
    __syncthreads();
    if (t < D_) {
        int i = t;
        float m = -1e30f;
        for (int j = 0; j <= i; j++) m = fmaxf(m, sp[i][j]);
        float sum = 0.f;
        for (int j = 0; j <= i; j++) { float e = expf(sp[i][j] - m); sp[i][j] = e; sum += e; }
        float inv = 1.0f / sum;
        for (int j = 0; j <= i; j++) sp[i][j] *= inv;
        for (int j = i + 1; j < D_; j++) sp[i][j] = 0.f;
    }
    __syncthreads();
    for (int idx = t; idx < D_*HD_; idx += 128) {
        int i = idx / HD_, c = idx - i*HD_;
        float acc = 0.f;
        for (int j = 0; j <= i; j++) acc = fmaf(sp[i][j], sv[j][c], acc);
        g_o[((long long)((b*D_ + i)*L_ + l))*H_ + h*HD_ + c] = acc;
    }
}

// ---------------- x_src = zL - x_prior, accumulate recon_attn sum ----------------
__global__ void xsrc_kernel(const float* __restrict__ zL, const float* __restrict__ xp,
                            float* __restrict__ xs) {
    long long base = (long long)blockIdx.x * H_ + threadIdx.x;
    float d0 = zL[base]     - xp[base];
    float d1 = zL[base+256] - xp[base+256];
    float d2 = zL[base+512] - xp[base+512];
    xs[base] = d0; xs[base+256] = d1; xs[base+512] = d2;
    __shared__ float sh[33];
    float s = blockReduceSum(d0*d0 + d1*d1 + d2*d2, sh);
    if (threadIdx.x == 0) atomicAdd(&g_acc[0], (double)s);
}

// ---------------- off[f] = bias_enc[f] - dot(bias_pre, enc[f,:]) ----------------
__global__ void off_kernel(const float* __restrict__ enc, const float* __restrict__ bp,
                           const float* __restrict__ be) {
    int f = blockIdx.x, t = threadIdx.x; // 128
    const float* er = enc + (long long)f * H_;
    float s = 0.f;
    for (int c = t; c < H_; c += 128) s = fmaf(bp[c], er[c], s);
    __shared__ float sh[33];
    s = blockReduceSum(s, sh);
    if (t == 0) g_off[f] = be[f] - s;
}

// ---------------- transpose dictionary_dec [H,F] -> g_decT [F,H] ----------------
__global__ void transpose_dec_kernel(const float* __restrict__ dec) {
    __shared__ float tile[32][33];
    int bx = blockIdx.x * 32, by = blockIdx.y * 32; // bx: f, by: h
    int f = bx + threadIdx.x, h = by + threadIdx.y;
    #pragma unroll
    for (int i = 0; i < 32; i += 8)
        tile[threadIdx.y + i][threadIdx.x] = dec[(long long)(h + i) * F_ + f];
    __syncthreads();
    int f2 = bx + threadIdx.y, h2 = by + threadIdx.x;
    #pragma unroll
    for (int i = 0; i < 32; i += 8)
        g_decT[(long long)(f2 + i) * H_ + h2] = tile[threadIdx.x][threadIdx.y + i];
}

// ---------------- exact per-row top-64 + sparse decode + losses ----------------
__global__ void __launch_bounds__(256) topk_decode_kernel(
    const float* __restrict__ xsrc, float* __restrict__ zn, float* __restrict__ xtgt)
{
    int row = blockIdx.x, t = threadIdx.x;
    const float* src = g_big + (long long)row * F_;
    float v[16]; unsigned u[16];
    const float4* s4 = (const float4*)(src + t * 16);
    #pragma unroll
    for (int i = 0; i < 4; i++) {
        float4 q = s4[i];
        v[4*i+0] = q.x; v[4*i+1] = q.y; v[4*i+2] = q.z; v[4*i+3] = q.w;
    }
    #pragma unroll
    for (int i = 0; i < 16; i++) u[i] = (v[i] > 0.f) ? __float_as_uint(v[i]) : 0u;

    // binary search for the 64th-largest value's bits (values >= 0 -> uint order == float order)
    __shared__ int ish[33];
    unsigned thresh = 0;
    for (int bit = 31; bit >= 0; bit--) {
        unsigned cand = thresh | (1u << bit);
        int c = 0;
        #pragma unroll
        for (int i = 0; i < 16; i++) c += (u[i] >= cand) ? 1 : 0;
        c = blockReduceSumI(c, ish);
        if (c >= TOPK_) thresh = cand;
    }
    int gt_local = 0, eq_local = 0;
    #pragma unroll
    for (int i = 0; i < 16; i++) { gt_local += (u[i] > thresh); eq_local += (u[i] == thresh); }
    __shared__ int sgt[256], seqc[256];
    sgt[t] = gt_local; seqc[t] = eq_local;
    __syncthreads();
    int gt_pre = 0, eq_pre = 0, gt_tot = 0;
    for (int i = 0; i < 256; i++) {
        int g = sgt[i]; gt_tot += g;
        if (i < t) { gt_pre += g; eq_pre += seqc[i]; }
    }
    int need_eq = TOPK_ - gt_tot;   // ties kept by lowest index (matches lax.top_k)

    __shared__ int sidx[TOPK_]; __shared__ float sval[TOPK_];
    float rsum = 0.f;
    int gpos = gt_pre, epos = eq_pre;
    #pragma unroll
    for (int i = 0; i < 16; i++) {
        float val = v[i]; bool keep = false; int pos = 0;
        if (u[i] > thresh) { keep = true; pos = gpos++; }
        else if (u[i] == thresh) { if (epos < need_eq) { keep = true; pos = gt_tot + epos; } epos++; }
        float w = keep ? val : 0.f;
        if (keep) { sidx[pos] = t*16 + i; sval[pos] = w; rsum += w; }
        v[i] = w;
    }
    // dense sparse-code output row
    float4* z4 = (float4*)(zn + (long long)row * F_ + t * 16);
    #pragma unroll
    for (int i = 0; i < 4; i++) z4[i] = make_float4(v[4*i], v[4*i+1], v[4*i+2], v[4*i+3]);

    __shared__ float fsh[33];
    float tot = blockReduceSum(rsum, fsh);
    if (t == 0) atomicAdd(&g_acc[2], (double)tot);

    // sparse decode: x_tgt[row,h] = sum_p sval[p] * decT[f_p, h]
    float a0 = 0.f, a1 = 0.f, a2 = 0.f;
    #pragma unroll 4
    for (int p = 0; p < TOPK_; p++) {
        float val = sval[p];
        const float* er = g_decT + (long long)sidx[p] * H_;
        a0 = fmaf(val, er[t],       a0);
        a1 = fmaf(val, er[t + 256], a1);
        a2 = fmaf(val, er[t + 512], a2);
    }
    long long base = (long long)row * H_;
    float s0 = xsrc[base+t], s1 = xsrc[base+t+256], s2 = xsrc[base+t+512];
    xtgt[base+t] = a0; xtgt[base+t+256] = a1; xtgt[base+t+512] = a2;
    float d0 = a0 - s0, d1 = a1 - s1, d2 = a2 - s2;
    float ss = blockReduceSum(d0*d0 + d1*d1 + d2*d2, fsh);
    if (t == 0) atomicAdd(&g_acc[1], (double)ss);
}

__global__ void finalize_kernel(float* __restrict__ out) {
    double nh = (double)NROWS_ * (double)H_;
    double ra = g_acc[0] / nh;            // recon_loss_attn
    double rc = g_acc[1] / nh;            // recon_loss
    double sp = g_acc[2] / ((double)NROWS_ * (double)F_);  // sparse_loss
    out[0] = (float)(ra + rc + 1e-3 * sp);
    out[1] = (float)rc;
    out[2] = (float)ra;
    out[3] = (float)sp;
}

// ---------------- host ----------------
extern "C" void kernel_launch(void* const* d_in, const int* in_sizes, int n_in,
                              void* d_out, int out_size) {
    const float* zL    = (const float*)d_in[0];
    const float* Wq_l  = (const float*)d_in[1];
    const float* Wk_l  = (const float*)d_in[2];
    const float* Wv_l  = (const float*)d_in[3];
    const float* Wo_l  = (const float*)d_in[4];
    const float* gl    = (const float*)d_in[5];
    const float* bl    = (const float*)d_in[6];
    const float* Wq_d  = (const float*)d_in[7];
    const float* Wk_d  = (const float*)d_in[8];
    const float* Wv_d  = (const float*)d_in[9];
    const float* Wo_d  = (const float*)d_in[10];
    const float* gd    = (const float*)d_in[11];
    const float* bd    = (const float*)d_in[12];
    const float* enc   = (const float*)d_in[13];
    const float* dec   = (const float*)d_in[14];
    const float* bpre  = (const float*)d_in[15];
    const float* benc  = (const float*)d_in[16];
    const float* qtok  = (const float*)d_in[17];

    const long long NHs = (long long)NROWS_ * H_;
    float* out      = (float*)d_out;
    float* o_xprior = out + 4;
    float* o_xtgt   = o_xprior + NHs;
    float* o_xsrc   = o_xtgt + NHs;
    float* o_zn     = o_xsrc + NHs;

    float *px, *pln, *pq, *pk, *pv, *po, *px1, *pbig, *poff;
    cudaGetSymbolAddress((void**)&px,   g_x);
    cudaGetSymbolAddress((void**)&pln,  g_ln);
    cudaGetSymbolAddress((void**)&pq,   g_q);
    cudaGetSymbolAddress((void**)&pk,   g_k);
    cudaGetSymbolAddress((void**)&pv,   g_v);
    cudaGetSymbolAddress((void**)&po,   g_o);
    cudaGetSymbolAddress((void**)&px1,  g_x1);
    cudaGetSymbolAddress((void**)&pbig, g_big);
    cudaGetSymbolAddress((void**)&poff, g_off);

    zero_acc_kernel<<<1, 32>>>();
    build_ln_kernel<<<NROWS_, 256>>>(zL, qtok, gl, bl);

    dim3 gP(H_/128, NROWS_/128, 1);   // 6 x 192
    // L-attention projections
    gemm_kernel<1><<<gP, 256>>>(pln, Wq_l, pq, NROWS_, H_, H_, H_, H_, H_, 1,
                                0,0,0,0,0,0, 1.f, nullptr, nullptr, 0, 0);
    gemm_kernel<1><<<gP, 256>>>(pln, Wk_l, pk, NROWS_, H_, H_, H_, H_, H_, 1,
                                0,0,0,0,0,0, 1.f, nullptr, nullptr, 0, 0);
    gemm_kernel<1><<<gP, 256>>>(pln, Wv_l, pv, NROWS_, H_, H_, H_, H_, H_, 1,
                                0,0,0,0,0,0, 1.f, nullptr, nullptr, 0, 0);
    // scores: per (bd,h): [512,96] x [512,96]^T -> g_big
    float scal = 1.0f / sqrtf((float)HD_);
    dim3 gS(4, 4, BD_ * NHD_);
    gemm_kernel<1><<<gS, 256>>>(pq, pk, pbig, 512, 512, HD_, H_, H_, 512, NHD_,
                                393216LL, 96LL, 393216LL, 96LL, 2097152LL, 262144LL,
                                scal, nullptr, nullptr, 0, 0);
    softmax_kernel<<<BD_ * NHD_ * 512, 128>>>();
    // PV: [512,512] x [512,96] -> g_o
    dim3 gPV(1, 4, BD_ * NHD_);
    gemm_kernel<0><<<gPV, 256>>>(pbig, pv, po, 512, HD_, 512, 512, H_, H_, NHD_,
                                 2097152LL, 262144LL, 393216LL, 96LL, 393216LL, 96LL,
                                 1.f, nullptr, nullptr, 0, 0);
    // x1 = x + o @ Wo_l^T
    gemm_kernel<1><<<gP, 256>>>(po, Wo_l, px1, NROWS_, H_, H_, H_, H_, H_, 1,
                                0,0,0,0,0,0, 1.f, nullptr, px, H_, 0);
    // D-attention
    ln_d_kernel<<<NROWS_, 256>>>(gd, bd);
    gemm_kernel<1><<<gP, 256>>>(pln, Wq_d, pq, NROWS_, H_, H_, H_, H_, H_, 1,
                                0,0,0,0,0,0, 1.f, nullptr, nullptr, 0, 0);
    gemm_kernel<1><<<gP, 256>>>(pln, Wk_d, pk, NROWS_, H_, H_, H_, H_, H_, 1,
                                0,0,0,0,0,0, 1.f, nullptr, nullptr, 0, 0);
    gemm_kernel<1><<<gP, 256>>>(pln, Wv_d, pv, NROWS_, H_, H_, H_, H_, H_, 1,
                                0,0,0,0,0,0, 1.f, nullptr, nullptr, 0, 0);
    dattn_kernel<<<B_ * L_ * NHD_, 128>>>();
    // x_prior = x1 + o @ Wo_d^T  (written straight to output)
    gemm_kernel<1><<<gP, 256>>>(po, Wo_d, o_xprior, NROWS_, H_, H_, H_, H_, H_, 1,
                                0,0,0,0,0,0, 1.f, nullptr, px1, H_, 0);
    // x_src + recon_attn
    xsrc_kernel<<<NROWS_, 256>>>(zL, o_xprior, o_xsrc);
    // SAE encoder
    off_kernel<<<F_, 128>>>(enc, bpre, benc);
    transpose_dec_kernel<<<dim3(F_/32, H_/32), dim3(32, 8)>>>(dec);
    dim3 gE(F_/128, NROWS_/128, 1);   // 32 x 192
    gemm_kernel<1><<<gE, 256>>>(o_xsrc, enc, pbig, NROWS_, F_, H_, H_, H_, F_, 1,
                                0,0,0,0,0,0, 1.f, poff, nullptr, 0, 1);
    // top-k + decode + losses
    topk_decode_kernel<<<NROWS_, 256>>>(o_xsrc, o_zn, o_xtgt);
    finalize_kernel<<<1, 1>>>(out);
}

// round 4
// speedup vs baseline: 1.0096x; 1.0096x over previous
#include <cuda_runtime.h>
#include <math.h>

#define B_ 4
#define D_ 12
#define L_ 512
#define H_ 768
#define F_ 4096
#define NHD_ 8
#define HD_ 96
#define TOPK_ 64
#define NROWS_ (B_*D_*L_)            /* 24576 */
#define BD_ (B_*D_)                  /* 48 */

// ---------------- static scratch (no allocations allowed) ----------------
__device__ float g_x  [NROWS_*H_];
__device__ float g_ln [NROWS_*H_];
__device__ float g_q  [NROWS_*H_];
__device__ float g_k  [NROWS_*H_];
__device__ float g_v  [NROWS_*H_];
__device__ float g_o  [NROWS_*H_];
__device__ float g_x1 [NROWS_*H_];
__device__ float g_big[100663296];   // scores (384*512*512) then z_dense (24576*4096)
__device__ float g_decT[F_*H_];      // transposed dictionary_dec
__device__ float g_off[F_];
__device__ double g_acc[3];          // [0]=sum(xprior-zL)^2  [1]=sum(xtgt-xsrc)^2  [2]=sum z

// ---------------- f32x2 packed helpers ----------------
__device__ __forceinline__ unsigned long long dup_f32x2(float x) {
    unsigned long long r;
    asm("mov.b64 %0, {%1, %1};" : "=l"(r) : "f"(x));
    return r;
}
__device__ __forceinline__ void fma_f32x2(unsigned long long& d,
                                          unsigned long long a, unsigned long long b) {
    asm("fma.rn.f32x2 %0, %1, %2, %0;" : "+l"(d) : "l"(a), "l"(b));
}
__device__ __forceinline__ void unpack_f32x2(float& lo, float& hi, unsigned long long v) {
    asm("mov.b64 {%0, %1}, %2;" : "=f"(lo), "=f"(hi) : "l"(v));
}

// ---------------- reductions ----------------
__device__ __forceinline__ float blockReduceSum(float v, float* sh) {
    int t = threadIdx.x, lane = t & 31, w = t >> 5, nw = blockDim.x >> 5;
    #pragma unroll
    for (int o = 16; o; o >>= 1) v += __shfl_down_sync(0xffffffffu, v, o);
    __syncthreads();
    if (lane == 0) sh[w] = v;
    __syncthreads();
    if (t == 0) { float s = 0.f; for (int i = 0; i < nw; i++) s += sh[i]; sh[32] = s; }
    __syncthreads();
    return sh[32];
}
__device__ __forceinline__ float blockReduceMax(float v, float* sh) {
    int t = threadIdx.x, lane = t & 31, w = t >> 5, nw = blockDim.x >> 5;
    #pragma unroll
    for (int o = 16; o; o >>= 1) v = fmaxf(v, __shfl_down_sync(0xffffffffu, v, o));
    __syncthreads();
    if (lane == 0) sh[w] = v;
    __syncthreads();
    if (t == 0) { float m = sh[0]; for (int i = 1; i < nw; i++) m = fmaxf(m, sh[i]); sh[32] = m; }
    __syncthreads();
    return sh[32];
}
__device__ __forceinline__ int blockReduceSumI(int v, int* sh) {
    int t = threadIdx.x, lane = t & 31, w = t >> 5, nw = blockDim.x >> 5;
    #pragma unroll
    for (int o = 16; o; o >>= 1) v += __shfl_down_sync(0xffffffffu, v, o);
    __syncthreads();
    if (lane == 0) sh[w] = v;
    __syncthreads();
    if (t == 0) { int s = 0; for (int i = 0; i < nw; i++) s += sh[i]; sh[32] = s; }
    __syncthreads();
    return sh[32];
}

// ---------------- misc ----------------
__global__ void zero_acc_kernel() {
    if (threadIdx.x < 3) g_acc[threadIdx.x] = 0.0;
}

// x = concat(query_token, zL[:, :-1]) along depth; g_ln = layer_norm(x, g_l, b_l)
__global__ void build_ln_kernel(const float* __restrict__ zL, const float* __restrict__ qtok,
                                const float* __restrict__ gw, const float* __restrict__ bw) {
    int row = blockIdx.x, t = threadIdx.x;
    int l = row % L_, d = (row / L_) % D_, b = row / (L_ * D_);
    const float* src = (d == 0) ? qtok
                                : (zL + ((long long)((b*D_ + (d-1))*L_ + l))*H_);
    float v0 = src[t], v1 = src[t+256], v2 = src[t+512];
    long long base = (long long)row * H_;
    g_x[base+t] = v0; g_x[base+t+256] = v1; g_x[base+t+512] = v2;
    __shared__ float sh[33];
    float mean = blockReduceSum(v0+v1+v2, sh) * (1.0f/H_);
    float d0 = v0-mean, d1 = v1-mean, d2 = v2-mean;
    float var = blockReduceSum(d0*d0+d1*d1+d2*d2, sh) * (1.0f/H_);
    float inv = rsqrtf(var + 1e-5f);
    g_ln[base+t]     = d0*inv*gw[t]     + bw[t];
    g_ln[base+t+256] = d1*inv*gw[t+256] + bw[t+256];
    g_ln[base+t+512] = d2*inv*gw[t+512] + bw[t+512];
}

// g_ln = layer_norm(g_x1, g_d, b_d)
__global__ void ln_d_kernel(const float* __restrict__ gw, const float* __restrict__ bw) {
    int row = blockIdx.x, t = threadIdx.x;
    long long base = (long long)row * H_;
    float v0 = g_x1[base+t], v1 = g_x1[base+t+256], v2 = g_x1[base+t+512];
    __shared__ float sh[33];
    float mean = blockReduceSum(v0+v1+v2, sh) * (1.0f/H_);
    float d0 = v0-mean, d1 = v1-mean, d2 = v2-mean;
    float var = blockReduceSum(d0*d0+d1*d1+d2*d2, sh) * (1.0f/H_);
    float inv = rsqrtf(var + 1e-5f);
    g_ln[base+t]     = d0*inv*gw[t]     + bw[t];
    g_ln[base+t+256] = d1*inv*gw[t+256] + bw[t+256];
    g_ln[base+t+512] = d2*inv*gw[t+512] + bw[t+512];
}

// ---------------- f32x2 batched SGEMM: 128x128 tile, 128 threads, 16x8 microtile ----------------
// TRANSB=1: C[m,n] = alpha*sum_k A[m,k]*B[n,k]    TRANSB=0: C[m,n] = alpha*sum_k A[m,k]*B[k,n]
// + optional bias[n] + res[m,n] + relu.  Batched via bz=(z1,z2) strides. K mult of 8, Nn mult of 4.
// Accumulation order over k identical to a scalar k-sequential loop (bitwise-stable epilogue inputs).
template<int TRANSB>
__global__ void __launch_bounds__(128) gemm_kernel(
    const float* __restrict__ A, const float* __restrict__ Bm, float* __restrict__ C,
    int M, int Nn, int K, int lda, int ldb, int ldc,
    int zdiv,
    long long sA1, long long sA2, long long sB1, long long sB2,
    long long sC1, long long sC2,
    float alpha, const float* __restrict__ bias,
    const float* __restrict__ res, int ldres, int relu)
{
    __shared__ float As[8][128];
    __shared__ float Bs[8][128];
    int bz = blockIdx.z;
    int z1 = bz / zdiv, z2 = bz - z1 * zdiv;
    A  += z1*sA1 + z2*sA2;
    Bm += z1*sB1 + z2*sB2;
    C  += z1*sC1 + z2*sC2;
    int bm = blockIdx.y * 128, bn = blockIdx.x * 128;
    int t = threadIdx.x;
    int tx = t & 15, ty = t >> 4;        // tx -> 8 cols, ty -> 16 rows

    unsigned long long acc[8][8];        // [row-pair][col]; zero bits == (0.f,0.f)
    #pragma unroll
    for (int i = 0; i < 8; i++)
        #pragma unroll
        for (int j = 0; j < 8; j++) acc[i][j] = 0ull;

    // global-load thread maps
    int mA = t >> 1;              // 0..63 (+64 for second row)
    int kA = (t & 1) * 4;         // {0,4}
    int kB = t >> 4;              // 0..7   (TRANSB=0)
    int nB = (t & 15) * 8;        // 0..120 (TRANSB=0)

    float4 pa0, pa1, pb0, pb1;
    // prefetch k0 = 0
    {
        int gm0 = bm + mA, gm1 = bm + mA + 64;
        pa0 = make_float4(0.f,0.f,0.f,0.f); pa1 = pa0;
        if (gm0 < M) pa0 = *(const float4*)(A + (long long)gm0*lda + kA);
        if (gm1 < M) pa1 = *(const float4*)(A + (long long)gm1*lda + kA);
        if (TRANSB) {
            int gn0 = bn + mA, gn1 = bn + mA + 64;
            pb0 = make_float4(0.f,0.f,0.f,0.f); pb1 = pb0;
            if (gn0 < Nn) pb0 = *(const float4*)(Bm + (long long)gn0*ldb + kA);
            if (gn1 < Nn) pb1 = *(const float4*)(Bm + (long long)gn1*ldb + kA);
        } else {
            const float* bp = Bm + (long long)kB*ldb;
            int gn0 = bn + nB, gn1 = bn + nB + 4;
            pb0 = make_float4(0.f,0.f,0.f,0.f); pb1 = pb0;
            if (gn0 + 3 < Nn) pb0 = *(const float4*)(bp + gn0);
            if (gn1 + 3 < Nn) pb1 = *(const float4*)(bp + gn1);
        }
    }

    for (int k0 = 0; k0 < K; k0 += 8) {
        // commit prefetched tile to smem
        As[kA+0][mA]    = pa0.x; As[kA+1][mA]    = pa0.y; As[kA+2][mA]    = pa0.z; As[kA+3][mA]    = pa0.w;
        As[kA+0][mA+64] = pa1.x; As[kA+1][mA+64] = pa1.y; As[kA+2][mA+64] = pa1.z; As[kA+3][mA+64] = pa1.w;
        if (TRANSB) {
            Bs[kA+0][mA]    = pb0.x; Bs[kA+1][mA]    = pb0.y; Bs[kA+2][mA]    = pb0.z; Bs[kA+3][mA]    = pb0.w;
            Bs[kA+0][mA+64] = pb1.x; Bs[kA+1][mA+64] = pb1.y; Bs[kA+2][mA+64] = pb1.z; Bs[kA+3][mA+64] = pb1.w;
        } else {
            *(float4*)&Bs[kB][nB]     = pb0;
            *(float4*)&Bs[kB][nB + 4] = pb1;
        }
        __syncthreads();

        // prefetch next tile (hidden behind compute)
        int kn = k0 + 8;
        if (kn < K) {
            int gm0 = bm + mA, gm1 = bm + mA + 64;
            pa0 = make_float4(0.f,0.f,0.f,0.f); pa1 = pa0;
            if (gm0 < M) pa0 = *(const float4*)(A + (long long)gm0*lda + (kn + kA));
            if (gm1 < M) pa1 = *(const float4*)(A + (long long)gm1*lda + (kn + kA));
            if (TRANSB) {
                int gn0 = bn + mA, gn1 = bn + mA + 64;
                pb0 = make_float4(0.f,0.f,0.f,0.f); pb1 = pb0;
                if (gn0 < Nn) pb0 = *(const float4*)(Bm + (long long)gn0*ldb + (kn + kA));
                if (gn1 < Nn) pb1 = *(const float4*)(Bm + (long long)gn1*ldb + (kn + kA));
            } else {
                const float* bp = Bm + (long long)(kn + kB)*ldb;
                int gn0 = bn + nB, gn1 = bn + nB + 4;
                pb0 = make_float4(0.f,0.f,0.f,0.f); pb1 = pb0;
                if (gn0 + 3 < Nn) pb0 = *(const float4*)(bp + gn0);
                if (gn1 + 3 < Nn) pb1 = *(const float4*)(bp + gn1);
            }
        }

        #pragma unroll
        for (int kk = 0; kk < 8; kk++) {
            // B fragment: 8 cols, dup each into both f32x2 lanes
            float4 b0 = *(const float4*)&Bs[kk][tx*8];
            float4 b1 = *(const float4*)&Bs[kk][tx*8 + 4];
            unsigned long long bd[8];
            bd[0] = dup_f32x2(b0.x); bd[1] = dup_f32x2(b0.y);
            bd[2] = dup_f32x2(b0.z); bd[3] = dup_f32x2(b0.w);
            bd[4] = dup_f32x2(b1.x); bd[5] = dup_f32x2(b1.y);
            bd[6] = dup_f32x2(b1.z); bd[7] = dup_f32x2(b1.w);
            // A fragment: 16 rows = 8 natural f32x2 row-pairs
            union { float4 f4[4]; unsigned long long u[8]; } av;
            av.f4[0] = *(const float4*)&As[kk][ty*16];
            av.f4[1] = *(const float4*)&As[kk][ty*16 + 4];
            av.f4[2] = *(const float4*)&As[kk][ty*16 + 8];
            av.f4[3] = *(const float4*)&As[kk][ty*16 + 12];
            #pragma unroll
            for (int ip = 0; ip < 8; ip++)
                #pragma unroll
                for (int j = 0; j < 8; j++)
                    fma_f32x2(acc[ip][j], av.u[ip], bd[j]);
        }
        __syncthreads();
    }

    // epilogue
    #pragma unroll
    for (int ip = 0; ip < 8; ip++) {
        float lo[8], hi[8];
        #pragma unroll
        for (int j = 0; j < 8; j++) unpack_f32x2(lo[j], hi[j], acc[ip][j]);
        #pragma unroll
        for (int half = 0; half < 2; half++) {
            int gm = bm + ty*16 + ip*2 + half;
            if (gm >= M) continue;
            const float* vv = half ? hi : lo;
            long long crow = (long long)gm * ldc;
            long long rrow = (long long)gm * ldres;
            #pragma unroll
            for (int j = 0; j < 8; j++) {
                int gn = bn + tx*8 + j;
                if (gn >= Nn) continue;
                float x = vv[j] * alpha;
                if (bias) x += bias[gn];
                if (res)  x += res[rrow + gn];
                if (relu) x = fmaxf(x, 0.f);
                C[crow + gn] = x;
            }
        }
    }
}

// ---------------- softmax over rows of 512 (L-attn scores, in place in g_big) ----------------
__global__ void softmax_kernel() {
    float* p = g_big + (long long)blockIdx.x * 512;
    int t = threadIdx.x; // 128
    float4 v = ((float4*)p)[t];
    __shared__ float sh[33];
    float m = blockReduceMax(fmaxf(fmaxf(v.x, v.y), fmaxf(v.z, v.w)), sh);
    v.x = expf(v.x - m); v.y = expf(v.y - m); v.z = expf(v.z - m); v.w = expf(v.w - m);
    float s = blockReduceSum(v.x + v.y + v.z + v.w, sh);
    float inv = 1.0f / s;
    v.x *= inv; v.y *= inv; v.z *= inv; v.w *= inv;
    ((float4*)p)[t] = v;
}

// ---------------- causal attention over D (seq len 12), per (b,l,h) ----------------
__global__ void dattn_kernel() {
    int bid = blockIdx.x;
    int h = bid % NHD_;
    int l = (bid / NHD_) % L_;
    int b = bid / (NHD_ * L_);
    __shared__ float sq[D_][HD_], sk[D_][HD_], sv[D_][HD_];
    __shared__ float sp[D_][D_];
    int t = threadIdx.x; // 128
    for (int idx = t; idx < D_*HD_; idx += 128) {
        int d = idx / HD_, c = idx - d*HD_;
        long long g = ((long long)((b*D_ + d)*L_ + l))*H_ + h*HD_ + c;
        sq[d][c] = g_q[g]; sk[d][c] = g_k[g]; sv[d][c] = g_v[g];
    }
    __syncthreads();
    const float scale = rsqrtf((float)HD_);
    for (int idx = t; idx < D_*D_; idx += 128) {
        int i = idx / D_, j = idx - i*D_;
        float s = 0.f;
        if (j <= i) {
            #pragma unroll 8
            for (int c = 0; c < HD_; c++) s = fmaf(sq[i][c], sk[j][c], s);
            s *= scale;
        }
        sp[i][j] = s;
    }
    __syncthreads();
    if (t < D_) {
        int i = t;
        float m = -1e30f;
        for (int j = 0; j <= i; j++) m = fmaxf(m, sp[i][j]);
        float sum = 0.f;
        for (int j = 0; j <= i; j++) { float e = expf(sp[i][j] - m); sp[i][j] = e; sum += e; }
        float inv = 1.0f / sum;
        for (int j = 0; j <= i; j++) sp[i][j] *= inv;
        for (int j = i + 1; j < D_; j++) sp[i][j] = 0.f;
    }
    __syncthreads();
    for (int idx = t; idx < D_*HD_; idx += 128) {
        int i = idx / HD_, c = idx - i*HD_;
        float acc = 0.f;
        for (int j = 0; j <= i; j++) acc = fmaf(sp[i][j], sv[j][c], acc);
        g_o[((long long)((b*D_ + i)*L_ + l))*H_ + h*HD_ + c] = acc;
    }
}

// ---------------- x_src = zL - x_prior, accumulate recon_attn sum ----------------
__global__ void xsrc_kernel(const float* __restrict__ zL, const float* __restrict__ xp,
                            float* __restrict__ xs) {
    long long base = (long long)blockIdx.x * H_ + threadIdx.x;
    float d0 = zL[base]     - xp[base];
    float d1 = zL[base+256] - xp[base+256];
    float d2 = zL[base+512] - xp[base+512];
    xs[base] = d0; xs[base+256] = d1; xs[base+512] = d2;
    __shared__ float sh[33];
    float s = blockReduceSum(d0*d0 + d1*d1 + d2*d2, sh);
    if (threadIdx.x == 0) atomicAdd(&g_acc[0], (double)s);
}

// ---------------- off[f] = bias_enc[f] - dot(bias_pre, enc[f,:]) ----------------
__global__ void off_kernel(const float* __restrict__ enc, const float* __restrict__ bp,
                           const float* __restrict__ be) {
    int f = blockIdx.x, t = threadIdx.x; // 128
    const float* er = enc + (long long)f * H_;
    float s = 0.f;
    for (int c = t; c < H_; c += 128) s = fmaf(bp[c], er[c], s);
    __shared__ float sh[33];
    s = blockReduceSum(s, sh);
    if (t == 0) g_off[f] = be[f] - s;
}

// ---------------- transpose dictionary_dec [H,F] -> g_decT [F,H] ----------------
__global__ void transpose_dec_kernel(const float* __restrict__ dec) {
    __shared__ float tile[32][33];
    int bx = blockIdx.x * 32, by = blockIdx.y * 32; // bx: f, by: h
    int f = bx + threadIdx.x, h = by + threadIdx.y;
    #pragma unroll
    for (int i = 0; i < 32; i += 8)
        tile[threadIdx.y + i][threadIdx.x] = dec[(long long)(h + i) * F_ + f];
    __syncthreads();
    int f2 = bx + threadIdx.y, h2 = by + threadIdx.x;
    #pragma unroll
    for (int i = 0; i < 32; i += 8)
        g_decT[(long long)(f2 + i) * H_ + h2] = tile[threadIdx.x][threadIdx.y + i];
}

// ---------------- exact per-row top-64 + sparse decode + losses ----------------
__global__ void __launch_bounds__(256) topk_decode_kernel(
    const float* __restrict__ xsrc, float* __restrict__ zn, float* __restrict__ xtgt)
{
    int row = blockIdx.x, t = threadIdx.x;
    const float* src = g_big + (long long)row * F_;
    float v[16]; unsigned u[16];
    const float4* s4 = (const float4*)(src + t * 16);
    #pragma unroll
    for (int i = 0; i < 4; i++) {
        float4 q = s4[i];
        v[4*i+0] = q.x; v[4*i+1] = q.y; v[4*i+2] = q.z; v[4*i+3] = q.w;
    }
    #pragma unroll
    for (int i = 0; i < 16; i++) u[i] = (v[i] > 0.f) ? __float_as_uint(v[i]) : 0u;

    // binary search for the 64th-largest value's bits (values >= 0 -> uint order == float order)
    __shared__ int ish[33];
    unsigned thresh = 0;
    for (int bit = 31; bit >= 0; bit--) {
        unsigned cand = thresh | (1u << bit);
        int c = 0;
        #pragma unroll
        for (int i = 0; i < 16; i++) c += (u[i] >= cand) ? 1 : 0;
        c = blockReduceSumI(c, ish);
        if (c >= TOPK_) thresh = cand;
    }
    int gt_local = 0, eq_local = 0;
    #pragma unroll
    for (int i = 0; i < 16; i++) { gt_local += (u[i] > thresh); eq_local += (u[i] == thresh); }
    __shared__ int sgt[256], seqc[256];
    sgt[t] = gt_local; seqc[t] = eq_local;
    __syncthreads();
    int gt_pre = 0, eq_pre = 0, gt_tot = 0;
    for (int i = 0; i < 256; i++) {
        int g = sgt[i]; gt_tot += g;
        if (i < t) { gt_pre += g; eq_pre += seqc[i]; }
    }
    int need_eq = TOPK_ - gt_tot;   // ties kept by lowest index (matches lax.top_k)

    __shared__ int sidx[TOPK_]; __shared__ float sval[TOPK_];
    float rsum = 0.f;
    int gpos = gt_pre, epos = eq_pre;
    #pragma unroll
    for (int i = 0; i < 16; i++) {
        float val = v[i]; bool keep = false; int pos = 0;
        if (u[i] > thresh) { keep = true; pos = gpos++; }
        else if (u[i] == thresh) { if (epos < need_eq) { keep = true; pos = gt_tot + epos; } epos++; }
        float w = keep ? val : 0.f;
        if (keep) { sidx[pos] = t*16 + i; sval[pos] = w; rsum += w; }
        v[i] = w;
    }
    // dense sparse-code output row
    float4* z4 = (float4*)(zn + (long long)row * F_ + t * 16);
    #pragma unroll
    for (int i = 0; i < 4; i++) z4[i] = make_float4(v[4*i], v[4*i+1], v[4*i+2], v[4*i+3]);

    __shared__ float fsh[33];
    float tot = blockReduceSum(rsum, fsh);
    if (t == 0) atomicAdd(&g_acc[2], (double)tot);

    // sparse decode: x_tgt[row,h] = sum_p sval[p] * decT[f_p, h]
    float a0 = 0.f, a1 = 0.f, a2 = 0.f;
    #pragma unroll 4
    for (int p = 0; p < TOPK_; p++) {
        float val = sval[p];
        const float* er = g_decT + (long long)sidx[p] * H_;
        a0 = fmaf(val, er[t],       a0);
        a1 = fmaf(val, er[t + 256], a1);
        a2 = fmaf(val, er[t + 512], a2);
    }
    long long base = (long long)row * H_;
    float s0 = xsrc[base+t], s1 = xsrc[base+t+256], s2 = xsrc[base+t+512];
    xtgt[base+t] = a0; xtgt[base+t+256] = a1; xtgt[base+t+512] = a2;
    float d0 = a0 - s0, d1 = a1 - s1, d2 = a2 - s2;
    float ss = blockReduceSum(d0*d0 + d1*d1 + d2*d2, fsh);
    if (t == 0) atomicAdd(&g_acc[1], (double)ss);
}

__global__ void finalize_kernel(float* __restrict__ out) {
    double nh = (double)NROWS_ * (double)H_;
    double ra = g_acc[0] / nh;            // recon_loss_attn
    double rc = g_acc[1] / nh;            // recon_loss
    double sp = g_acc[2] / ((double)NROWS_ * (double)F_);  // sparse_loss
    out[0] = (float)(ra + rc + 1e-3 * sp);
    out[1] = (float)rc;
    out[2] = (float)ra;
    out[3] = (float)sp;
}

// ---------------- host ----------------
extern "C" void kernel_launch(void* const* d_in, const int* in_sizes, int n_in,
                              void* d_out, int out_size) {
    const float* zL    = (const float*)d_in[0];
    const float* Wq_l  = (const float*)d_in[1];
    const float* Wk_l  = (const float*)d_in[2];
    const float* Wv_l  = (const float*)d_in[3];
    const float* Wo_l  = (const float*)d_in[4];
    const float* gl    = (const float*)d_in[5];
    const float* bl    = (const float*)d_in[6];
    const float* Wq_d  = (const float*)d_in[7];
    const float* Wk_d  = (const float*)d_in[8];
    const float* Wv_d  = (const float*)d_in[9];
    const float* Wo_d  = (const float*)d_in[10];
    const float* gd    = (const float*)d_in[11];
    const float* bd    = (const float*)d_in[12];
    const float* enc   = (const float*)d_in[13];
    const float* dec   = (const float*)d_in[14];
    const float* bpre  = (const float*)d_in[15];
    const float* benc  = (const float*)d_in[16];
    const float* qtok  = (const float*)d_in[17];

    const long long NHs = (long long)NROWS_ * H_;
    float* out      = (float*)d_out;
    float* o_xprior = out + 4;
    float* o_xtgt   = o_xprior + NHs;
    float* o_xsrc   = o_xtgt + NHs;
    float* o_zn     = o_xsrc + NHs;

    float *px, *pln, *pq, *pk, *pv, *po, *px1, *pbig, *poff;
    cudaGetSymbolAddress((void**)&px,   g_x);
    cudaGetSymbolAddress((void**)&pln,  g_ln);
    cudaGetSymbolAddress((void**)&pq,   g_q);
    cudaGetSymbolAddress((void**)&pk,   g_k);
    cudaGetSymbolAddress((void**)&pv,   g_v);
    cudaGetSymbolAddress((void**)&po,   g_o);
    cudaGetSymbolAddress((void**)&px1,  g_x1);
    cudaGetSymbolAddress((void**)&pbig, g_big);
    cudaGetSymbolAddress((void**)&poff, g_off);

    zero_acc_kernel<<<1, 32>>>();
    build_ln_kernel<<<NROWS_, 256>>>(zL, qtok, gl, bl);

    dim3 gP(H_/128, NROWS_/128, 1);   // 6 x 192
    // L-attention projections
    gemm_kernel<1><<<gP, 128>>>(pln, Wq_l, pq, NROWS_, H_, H_, H_, H_, H_, 1,
                                0,0,0,0,0,0, 1.f, nullptr, nullptr, 0, 0);
    gemm_kernel<1><<<gP, 128>>>(pln, Wk_l, pk, NROWS_, H_, H_, H_, H_, H_, 1,
                                0,0,0,0,0,0, 1.f, nullptr, nullptr, 0, 0);
    gemm_kernel<1><<<gP, 128>>>(pln, Wv_l, pv, NROWS_, H_, H_, H_, H_, H_, 1,
                                0,0,0,0,0,0, 1.f, nullptr, nullptr, 0, 0);
    // scores: per (bd,h): [512,96] x [512,96]^T -> g_big
    float scal = 1.0f / sqrtf((float)HD_);
    dim3 gS(4, 4, BD_ * NHD_);
    gemm_kernel<1><<<gS, 128>>>(pq, pk, pbig, 512, 512, HD_, H_, H_, 512, NHD_,
                                393216LL, 96LL, 393216LL, 96LL, 2097152LL, 262144LL,
                                scal, nullptr, nullptr, 0, 0);
    softmax_kernel<<<BD_ * NHD_ * 512, 128>>>();
    // PV: [512,512] x [512,96] -> g_o
    dim3 gPV(1, 4, BD_ * NHD_);
    gemm_kernel<0><<<gPV, 128>>>(pbig, pv, po, 512, HD_, 512, 512, H_, H_, NHD_,
                                 2097152LL, 262144LL, 393216LL, 96LL, 393216LL, 96LL,
                                 1.f, nullptr, nullptr, 0, 0);
    // x1 = x + o @ Wo_l^T
    gemm_kernel<1><<<gP, 128>>>(po, Wo_l, px1, NROWS_, H_, H_, H_, H_, H_, 1,
                                0,0,0,0,0,0, 1.f, nullptr, px, H_, 0);
    // D-attention
    ln_d_kernel<<<NROWS_, 256>>>(gd, bd);
    gemm_kernel<1><<<gP, 128>>>(pln, Wq_d, pq, NROWS_, H_, H_, H_, H_, H_, 1,
                                0,0,0,0,0,0, 1.f, nullptr, nullptr, 0, 0);
    gemm_kernel<1><<<gP, 128>>>(pln, Wk_d, pk, NROWS_, H_, H_, H_, H_, H_, 1,
                                0,0,0,0,0,0, 1.f, nullptr, nullptr, 0, 0);
    gemm_kernel<1><<<gP, 128>>>(pln, Wv_d, pv, NROWS_, H_, H_, H_, H_, H_, 1,
                                0,0,0,0,0,0, 1.f, nullptr, nullptr, 0, 0);
    dattn_kernel<<<B_ * L_ * NHD_, 128>>>();
    // x_prior = x1 + o @ Wo_d^T  (written straight to output)
    gemm_kernel<1><<<gP, 128>>>(po, Wo_d, o_xprior, NROWS_, H_, H_, H_, H_, H_, 1,
                                0,0,0,0,0,0, 1.f, nullptr, px1, H_, 0);
    // x_src + recon_attn
    xsrc_kernel<<<NROWS_, 256>>>(zL, o_xprior, o_xsrc);
    // SAE encoder
    off_kernel<<<F_, 128>>>(enc, bpre, benc);
    transpose_dec_kernel<<<dim3(F_/32, H_/32), dim3(32, 8)>>>(dec);
    dim3 gE(F_/128, NROWS_/128, 1);   // 32 x 192
    gemm_kernel<1><<<gE, 128>>>(o_xsrc, enc, pbig, NROWS_, F_, H_, H_, H_, F_, 1,
                                0,0,0,0,0,0, 1.f, poff, nullptr, 0, 1);
    // top-k + decode + losses
    topk_decode_kernel<<<NROWS_, 256>>>(o_xsrc, o_zn, o_xtgt);
    finalize_kernel<<<1, 1>>>(out);
}

// round 11
// speedup vs baseline: 1.0845x; 1.0742x over previous
#include <cuda_runtime.h>
#include <cuda_fp16.h>
#include <math.h>
#include <stdint.h>

#define B_ 4
#define D_ 12
#define L_ 512
#define H_ 768
#define F_ 4096
#define NHD_ 8
#define HD_ 96
#define TOPK_ 64
#define NROWS_ (B_*D_*L_)            /* 24576 */
#define BD_ (B_*D_)                  /* 48 */
#define DELTA_ 2e-4f
#define BANDCAP_ 512

// ---------------- static scratch (no allocations allowed) ----------------
__device__ float g_x  [NROWS_*H_];
__device__ float g_ln [NROWS_*H_];
__device__ float g_q  [NROWS_*H_];
__device__ float g_k  [NROWS_*H_];
__device__ float g_v  [NROWS_*H_];
__device__ float g_o  [NROWS_*H_];
__device__ float g_x1 [NROWS_*H_];
__device__ float g_big[100663296];   // scores (384*512*512) then z_dense (24576*4096)
__device__ float g_decT[F_*H_];      // transposed dictionary_dec
__device__ float g_off[F_];
__device__ double g_acc[3];          // [0]=sum(xprior-zL)^2  [1]=sum(xtgt-xsrc)^2  [2]=sum z

// ---------------- mma.sync helper (legacy HMMA path, compiles on compute_103) ----------------
__device__ __forceinline__ void mma16816(float* c, const uint32_t* a, const uint32_t* b) {
    asm volatile("mma.sync.aligned.m16n8k16.row.col.f32.f16.f16.f32 "
        "{%0,%1,%2,%3}, {%4,%5,%6,%7}, {%8,%9}, {%0,%1,%2,%3};"
        : "+f"(c[0]), "+f"(c[1]), "+f"(c[2]), "+f"(c[3])
        : "r"(a[0]), "r"(a[1]), "r"(a[2]), "r"(a[3]), "r"(b[0]), "r"(b[1]));
}

// ---------------- fp16 3-pass split GEMM (ENCODER ONLY): C = A*B^T (+bias)(relu) ----------------
__global__ void __launch_bounds__(256) hgemm3_kernel(
    const float* __restrict__ A, const float* __restrict__ Bm, float* __restrict__ C,
    int K, int ldc, const float* __restrict__ bias,
    const float* __restrict__ res, int relu)
{
    __shared__ __half Ah[128][40], Al[128][40], Bh[128][40], Bl[128][40];
    int t = threadIdx.x;
    int warp = t >> 5, lane = t & 31;
    int g = lane >> 2, tg = lane & 3;
    int wm = warp >> 2, wn = warp & 3;       // 2 x 4 warp grid; warp tile 64m x 32n
    int bm = blockIdx.y * 128, bn = blockIdx.x * 128;

    float c[4][4][4];
    #pragma unroll
    for (int i = 0; i < 4; i++)
        #pragma unroll
        for (int j = 0; j < 4; j++)
            #pragma unroll
            for (int q = 0; q < 4; q++) c[i][j][q] = 0.f;

    const float* Abase = A + (long long)bm * K;
    const float* Bbase = Bm + (long long)bn * K;

    float4 pa[4], pb[4];
    #pragma unroll
    for (int j = 0; j < 4; j++) {
        int idx = t + j * 256;
        int row = idx >> 3, cf = (idx & 7) * 4;
        pa[j] = *(const float4*)(Abase + (long long)row * K + cf);
        pb[j] = *(const float4*)(Bbase + (long long)row * K + cf);
    }

    for (int kc = 0; kc < K; kc += 32) {
        #pragma unroll
        for (int j = 0; j < 4; j++) {
            int idx = t + j * 256;
            int row = idx >> 3, cf = (idx & 7) * 4;
            float av[4] = {pa[j].x, pa[j].y, pa[j].z, pa[j].w};
            float bv[4] = {pb[j].x, pb[j].y, pb[j].z, pb[j].w};
            __half ah[4], al[4], bh[4], bl[4];
            #pragma unroll
            for (int q = 0; q < 4; q++) {
                ah[q] = __float2half_rn(av[q]);
                al[q] = __float2half_rn(av[q] - __half2float(ah[q]));
                bh[q] = __float2half_rn(bv[q]);
                bl[q] = __float2half_rn(bv[q] - __half2float(bh[q]));
            }
            #pragma unroll
            for (int q = 0; q < 4; q++) {
                Ah[row][cf + q] = ah[q];
                Al[row][cf + q] = al[q];
                Bh[row][cf + q] = bh[q];
                Bl[row][cf + q] = bl[q];
            }
        }
        __syncthreads();

        if (kc + 32 < K) {
            #pragma unroll
            for (int j = 0; j < 4; j++) {
                int idx = t + j * 256;
                int row = idx >> 3, cf = (idx & 7) * 4;
                pa[j] = *(const float4*)(Abase + (long long)row * K + kc + 32 + cf);
                pb[j] = *(const float4*)(Bbase + (long long)row * K + kc + 32 + cf);
            }
        }

        #pragma unroll
        for (int ks = 0; ks < 32; ks += 16) {
            uint32_t aH[4][4], aL[4][4], bH[4][2], bL[4][2];
            #pragma unroll
            for (int mt = 0; mt < 4; mt++) {
                int r0 = wm * 64 + mt * 16 + g;
                aH[mt][0] = *(const uint32_t*)&Ah[r0    ][ks + 2*tg];
                aH[mt][1] = *(const uint32_t*)&Ah[r0 + 8][ks + 2*tg];
                aH[mt][2] = *(const uint32_t*)&Ah[r0    ][ks + 8 + 2*tg];
                aH[mt][3] = *(const uint32_t*)&Ah[r0 + 8][ks + 8 + 2*tg];
                aL[mt][0] = *(const uint32_t*)&Al[r0    ][ks + 2*tg];
                aL[mt][1] = *(const uint32_t*)&Al[r0 + 8][ks + 2*tg];
                aL[mt][2] = *(const uint32_t*)&Al[r0    ][ks + 8 + 2*tg];
                aL[mt][3] = *(const uint32_t*)&Al[r0 + 8][ks + 8 + 2*tg];
            }
            #pragma unroll
            for (int nt = 0; nt < 4; nt++) {
                int cn = wn * 32 + nt * 8 + g;
                bH[nt][0] = *(const uint32_t*)&Bh[cn][ks + 2*tg];
                bH[nt][1] = *(const uint32_t*)&Bh[cn][ks + 8 + 2*tg];
                bL[nt][0] = *(const uint32_t*)&Bl[cn][ks + 2*tg];
                bL[nt][1] = *(const uint32_t*)&Bl[cn][ks + 8 + 2*tg];
            }
            #pragma unroll
            for (int mt = 0; mt < 4; mt++)
                #pragma unroll
                for (int nt = 0; nt < 4; nt++) {
                    mma16816(c[mt][nt], aH[mt], bH[nt]);
                    mma16816(c[mt][nt], aL[mt], bH[nt]);
                    mma16816(c[mt][nt], aH[mt], bL[nt]);
                }
        }
        __syncthreads();
    }

    #pragma unroll
    for (int mt = 0; mt < 4; mt++) {
        #pragma unroll
        for (int hf = 0; hf < 2; hf++) {
            int m = bm + wm * 64 + mt * 16 + g + hf * 8;
            long long crow = (long long)m * ldc;
            #pragma unroll
            for (int nt = 0; nt < 4; nt++) {
                int n = bn + wn * 32 + nt * 8 + 2 * tg;
                float vx = c[mt][nt][hf * 2 + 0];
                float vy = c[mt][nt][hf * 2 + 1];
                if (bias) { vx += bias[n]; vy += bias[n + 1]; }
                if (res) {
                    float2 rv = *(const float2*)(res + crow + n);
                    vx += rv.x; vy += rv.y;
                }
                if (relu) { vx = fmaxf(vx, 0.f); vy = fmaxf(vy, 0.f); }
                float2 o2; o2.x = vx; o2.y = vy;
                *(float2*)(C + crow + n) = o2;
            }
        }
    }
}

// ---------------- f32x2 helpers ----------------
__device__ __forceinline__ unsigned long long dup_f32x2(float x) {
    unsigned long long r;
    asm("mov.b64 %0, {%1, %1};" : "=l"(r) : "f"(x));
    return r;
}
__device__ __forceinline__ void fma_f32x2(unsigned long long& d,
                                          unsigned long long a, unsigned long long b) {
    asm("fma.rn.f32x2 %0, %1, %2, %0;" : "+l"(d) : "l"(a), "l"(b));
}
__device__ __forceinline__ void unpack_f32x2(float& lo, float& hi, unsigned long long v) {
    asm("mov.b64 {%0, %1}, %2;" : "=f"(lo), "=f"(hi) : "l"(v));
}

// ---------------- reductions ----------------
__device__ __forceinline__ float blockReduceSum(float v, float* sh) {
    int t = threadIdx.x, lane = t & 31, w = t >> 5, nw = blockDim.x >> 5;
    #pragma unroll
    for (int o = 16; o; o >>= 1) v += __shfl_down_sync(0xffffffffu, v, o);
    __syncthreads();
    if (lane == 0) sh[w] = v;
    __syncthreads();
    if (t == 0) { float s = 0.f; for (int i = 0; i < nw; i++) s += sh[i]; sh[32] = s; }
    __syncthreads();
    return sh[32];
}
__device__ __forceinline__ float blockReduceMax(float v, float* sh) {
    int t = threadIdx.x, lane = t & 31, w = t >> 5, nw = blockDim.x >> 5;
    #pragma unroll
    for (int o = 16; o; o >>= 1) v = fmaxf(v, __shfl_down_sync(0xffffffffu, v, o));
    __syncthreads();
    if (lane == 0) sh[w] = v;
    __syncthreads();
    if (t == 0) { float m = sh[0]; for (int i = 1; i < nw; i++) m = fmaxf(m, sh[i]); sh[32] = m; }
    __syncthreads();
    return sh[32];
}
__device__ __forceinline__ int blockReduceSumI(int v, int* sh) {
    int t = threadIdx.x, lane = t & 31, w = t >> 5, nw = blockDim.x >> 5;
    #pragma unroll
    for (int o = 16; o; o >>= 1) v += __shfl_down_sync(0xffffffffu, v, o);
    __syncthreads();
    if (lane == 0) sh[w] = v;
    __syncthreads();
    if (t == 0) { int s = 0; for (int i = 0; i < nw; i++) s += sh[i]; sh[32] = s; }
    __syncthreads();
    return sh[32];
}

// ---------------- misc ----------------
__global__ void zero_acc_kernel() {
    if (threadIdx.x < 3) g_acc[threadIdx.x] = 0.0;
}

__global__ void build_ln_kernel(const float* __restrict__ zL, const float* __restrict__ qtok,
                                const float* __restrict__ gw, const float* __restrict__ bw) {
    int row = blockIdx.x, t = threadIdx.x;
    int l = row % L_, d = (row / L_) % D_, b = row / (L_ * D_);
    const float* src = (d == 0) ? qtok
                                : (zL + ((long long)((b*D_ + (d-1))*L_ + l))*H_);
    float v0 = src[t], v1 = src[t+256], v2 = src[t+512];
    long long base = (long long)row * H_;
    g_x[base+t] = v0; g_x[base+t+256] = v1; g_x[base+t+512] = v2;
    __shared__ float sh[33];
    float mean = blockReduceSum(v0+v1+v2, sh) * (1.0f/H_);
    float d0 = v0-mean, d1 = v1-mean, d2 = v2-mean;
    float var = blockReduceSum(d0*d0+d1*d1+d2*d2, sh) * (1.0f/H_);
    float inv = rsqrtf(var + 1e-5f);
    g_ln[base+t]     = d0*inv*gw[t]     + bw[t];
    g_ln[base+t+256] = d1*inv*gw[t+256] + bw[t+256];
    g_ln[base+t+512] = d2*inv*gw[t+512] + bw[t+512];
}

__global__ void ln_d_kernel(const float* __restrict__ gw, const float* __restrict__ bw) {
    int row = blockIdx.x, t = threadIdx.x;
    long long base = (long long)row * H_;
    float v0 = g_x1[base+t], v1 = g_x1[base+t+256], v2 = g_x1[base+t+512];
    __shared__ float sh[33];
    float mean = blockReduceSum(v0+v1+v2, sh) * (1.0f/H_);
    float d0 = v0-mean, d1 = v1-mean, d2 = v2-mean;
    float var = blockReduceSum(d0*d0+d1*d1+d2*d2, sh) * (1.0f/H_);
    float inv = rsqrtf(var + 1e-5f);
    g_ln[base+t]     = d0*inv*gw[t]     + bw[t];
    g_ln[base+t+256] = d1*inv*gw[t+256] + bw[t+256];
    g_ln[base+t+512] = d2*inv*gw[t+512] + bw[t+512];
}

// ---------------- f32x2 batched SGEMM (all GEMMs feeding top-k; bit-identical to round 4) ----------------
template<int TRANSB>
__global__ void __launch_bounds__(128) gemm_kernel(
    const float* __restrict__ A, const float* __restrict__ Bm, float* __restrict__ C,
    int M, int Nn, int K, int lda, int ldb, int ldc,
    int zdiv,
    long long sA1, long long sA2, long long sB1, long long sB2,
    long long sC1, long long sC2,
    float alpha, const float* __restrict__ bias,
    const float* __restrict__ res, int ldres, int relu)
{
    __shared__ float As[8][128];
    __shared__ float Bs[8][128];
    int bz = blockIdx.z;
    int z1 = bz / zdiv, z2 = bz - z1 * zdiv;
    A  += z1*sA1 + z2*sA2;
    Bm += z1*sB1 + z2*sB2;
    C  += z1*sC1 + z2*sC2;
    int bm = blockIdx.y * 128, bn = blockIdx.x * 128;
    int t = threadIdx.x;
    int tx = t & 15, ty = t >> 4;

    unsigned long long acc[8][8];
    #pragma unroll
    for (int i = 0; i < 8; i++)
        #pragma unroll
        for (int j = 0; j < 8; j++) acc[i][j] = 0ull;

    int mA = t >> 1;
    int kA = (t & 1) * 4;
    int kB = t >> 4;
    int nB = (t & 15) * 8;

    float4 pa0, pa1, pb0, pb1;
    {
        int gm0 = bm + mA, gm1 = bm + mA + 64;
        pa0 = make_float4(0.f,0.f,0.f,0.f); pa1 = pa0;
        if (gm0 < M) pa0 = *(const float4*)(A + (long long)gm0*lda + kA);
        if (gm1 < M) pa1 = *(const float4*)(A + (long long)gm1*lda + kA);
        if (TRANSB) {
            int gn0 = bn + mA, gn1 = bn + mA + 64;
            pb0 = make_float4(0.f,0.f,0.f,0.f); pb1 = pb0;
            if (gn0 < Nn) pb0 = *(const float4*)(Bm + (long long)gn0*ldb + kA);
            if (gn1 < Nn) pb1 = *(const float4*)(Bm + (long long)gn1*ldb + kA);
        } else {
            const float* bp = Bm + (long long)kB*ldb;
            int gn0 = bn + nB, gn1 = bn + nB + 4;
            pb0 = make_float4(0.f,0.f,0.f,0.f); pb1 = pb0;
            if (gn0 + 3 < Nn) pb0 = *(const float4*)(bp + gn0);
            if (gn1 + 3 < Nn) pb1 = *(const float4*)(bp + gn1);
        }
    }

    for (int k0 = 0; k0 < K; k0 += 8) {
        As[kA+0][mA]    = pa0.x; As[kA+1][mA]    = pa0.y; As[kA+2][mA]    = pa0.z; As[kA+3][mA]    = pa0.w;
        As[kA+0][mA+64] = pa1.x; As[kA+1][mA+64] = pa1.y; As[kA+2][mA+64] = pa1.z; As[kA+3][mA+64] = pa1.w;
        if (TRANSB) {
            Bs[kA+0][mA]    = pb0.x; Bs[kA+1][mA]    = pb0.y; Bs[kA+2][mA]    = pb0.z; Bs[kA+3][mA]    = pb0.w;
            Bs[kA+0][mA+64] = pb1.x; Bs[kA+1][mA+64] = pb1.y; Bs[kA+2][mA+64] = pb1.z; Bs[kA+3][mA+64] = pb1.w;
        } else {
            *(float4*)&Bs[kB][nB]     = pb0;
            *(float4*)&Bs[kB][nB + 4] = pb1;
        }
        __syncthreads();

        int kn = k0 + 8;
        if (kn < K) {
            int gm0 = bm + mA, gm1 = bm + mA + 64;
            pa0 = make_float4(0.f,0.f,0.f,0.f); pa1 = pa0;
            if (gm0 < M) pa0 = *(const float4*)(A + (long long)gm0*lda + (kn + kA));
            if (gm1 < M) pa1 = *(const float4*)(A + (long long)gm1*lda + (kn + kA));
            if (TRANSB) {
                int gn0 = bn + mA, gn1 = bn + mA + 64;
                pb0 = make_float4(0.f,0.f,0.f,0.f); pb1 = pb0;
                if (gn0 < Nn) pb0 = *(const float4*)(Bm + (long long)gn0*ldb + (kn + kA));
                if (gn1 < Nn) pb1 = *(const float4*)(Bm + (long long)gn1*ldb + (kn + kA));
            } else {
                const float* bp = Bm + (long long)(kn + kB)*ldb;
                int gn0 = bn + nB, gn1 = bn + nB + 4;
                pb0 = make_float4(0.f,0.f,0.f,0.f); pb1 = pb0;
                if (gn0 + 3 < Nn) pb0 = *(const float4*)(bp + gn0);
                if (gn1 + 3 < Nn) pb1 = *(const float4*)(bp + gn1);
            }
        }

        #pragma unroll
        for (int kk = 0; kk < 8; kk++) {
            float4 b0 = *(const float4*)&Bs[kk][tx*8];
            float4 b1 = *(const float4*)&Bs[kk][tx*8 + 4];
            unsigned long long bd[8];
            bd[0] = dup_f32x2(b0.x); bd[1] = dup_f32x2(b0.y);
            bd[2] = dup_f32x2(b0.z); bd[3] = dup_f32x2(b0.w);
            bd[4] = dup_f32x2(b1.x); bd[5] = dup_f32x2(b1.y);
            bd[6] = dup_f32x2(b1.z); bd[7] = dup_f32x2(b1.w);
            union { float4 f4[4]; unsigned long long u[8]; } av;
            av.f4[0] = *(const float4*)&As[kk][ty*16];
            av.f4[1] = *(const float4*)&As[kk][ty*16 + 4];
            av.f4[2] = *(const float4*)&As[kk][ty*16 + 8];
            av.f4[3] = *(const float4*)&As[kk][ty*16 + 12];
            #pragma unroll
            for (int ip = 0; ip < 8; ip++)
                #pragma unroll
                for (int j = 0; j < 8; j++)
                    fma_f32x2(acc[ip][j], av.u[ip], bd[j]);
        }
        __syncthreads();
    }

    #pragma unroll
    for (int ip = 0; ip < 8; ip++) {
        float lo[8], hi[8];
        #pragma unroll
        for (int j = 0; j < 8; j++) unpack_f32x2(lo[j], hi[j], acc[ip][j]);
        #pragma unroll
        for (int half = 0; half < 2; half++) {
            int gm = bm + ty*16 + ip*2 + half;
            if (gm >= M) continue;
            const float* vv = half ? hi : lo;
            long long crow = (long long)gm * ldc;
            long long rrow = (long long)gm * ldres;
            #pragma unroll
            for (int j = 0; j < 8; j++) {
                int gn = bn + tx*8 + j;
                if (gn >= Nn) continue;
                float x = vv[j] * alpha;
                if (bias) x += bias[gn];
                if (res)  x += res[rrow + gn];
                if (relu) x = fmaxf(x, 0.f);
                C[crow + gn] = x;
            }
        }
    }
}

// ---------------- softmax over rows of 512 ----------------
__global__ void softmax_kernel() {
    float* p = g_big + (long long)blockIdx.x * 512;
    int t = threadIdx.x; // 128
    float4 v = ((float4*)p)[t];
    __shared__ float sh[33];
    float m = blockReduceMax(fmaxf(fmaxf(v.x, v.y), fmaxf(v.z, v.w)), sh);
    v.x = expf(v.x - m); v.y = expf(v.y - m); v.z = expf(v.z - m); v.w = expf(v.w - m);
    float s = blockReduceSum(v.x + v.y + v.z + v.w, sh);
    float inv = 1.0f / s;
    v.x *= inv; v.y *= inv; v.z *= inv; v.w *= inv;
    ((float4*)p)[t] = v;
}

// ---------------- causal attention over D (seq len 12) ----------------
__global__ void dattn_kernel() {
    int bid = blockIdx.x;
    int h = bid % NHD_;
    int l = (bid / NHD_) % L_;
    int b = bid / (NHD_ * L_);
    __shared__ float sq[D_][HD_], sk[D_][HD_], sv[D_][HD_];
    __shared__ float sp[D_][D_];
    int t = threadIdx.x; // 128
    for (int idx = t; idx < D_*HD_; idx += 128) {
        int d = idx / HD_, c = idx - d*HD_;
        long long g = ((long long)((b*D_ + d)*L_ + l))*H_ + h*HD_ + c;
        sq[d][c] = g_q[g]; sk[d][c] = g_k[g]; sv[d][c] = g_v[g];
    }
    __syncthreads();
    const float scale = rsqrtf((float)HD_);
    for (int idx = t; idx < D_*D_; idx += 128) {
        int i = idx / D_, j = idx - i*D_;
        float s = 0.f;
        if (j <= i) {
            #pragma unroll 8
            for (int c = 0; c < HD_; c++) s = fmaf(sq[i][c], sk[j][c], s);
            s *= scale;
        }
        sp[i][j] = s;
    }
    __syncthreads();
    if (t < D_) {
        int i = t;
        float m = -1e30f;
        for (int j = 0; j <= i; j++) m = fmaxf(m, sp[i][j]);
        float sum = 0.f;
        for (int j = 0; j <= i; j++) { float e = expf(sp[i][j] - m); sp[i][j] = e; sum += e; }
        float inv = 1.0f / sum;
        for (int j = 0; j <= i; j++) sp[i][j] *= inv;
        for (int j = i + 1; j < D_; j++) sp[i][j] = 0.f;
    }
    __syncthreads();
    for (int idx = t; idx < D_*HD_; idx += 128) {
        int i = idx / HD_, c = idx - i*HD_;
        float acc = 0.f;
        for (int j = 0; j <= i; j++) acc = fmaf(sp[i][j], sv[j][c], acc);
        g_o[((long long)((b*D_ + i)*L_ + l))*H_ + h*HD_ + c] = acc;
    }
}

// ---------------- x_src = zL - x_prior ----------------
__global__ void xsrc_kernel(const float* __restrict__ zL, const float* __restrict__ xp,
                            float* __restrict__ xs) {
    long long base = (long long)blockIdx.x * H_ + threadIdx.x;
    float d0 = zL[base]     - xp[base];
    float d1 = zL[base+256] - xp[base+256];
    float d2 = zL[base+512] - xp[base+512];
    xs[base] = d0; xs[base+256] = d1; xs[base+512] = d2;
    __shared__ float sh[33];
    float s = blockReduceSum(d0*d0 + d1*d1 + d2*d2, sh);
    if (threadIdx.x == 0) atomicAdd(&g_acc[0], (double)s);
}

// ---------------- off[f] = bias_enc[f] - dot(bias_pre, enc[f,:]) ----------------
__global__ void off_kernel(const float* __restrict__ enc, const float* __restrict__ bp,
                           const float* __restrict__ be) {
    int f = blockIdx.x, t = threadIdx.x; // 128
    const float* er = enc + (long long)f * H_;
    float s = 0.f;
    for (int c = t; c < H_; c += 128) s = fmaf(bp[c], er[c], s);
    __shared__ float sh[33];
    s = blockReduceSum(s, sh);
    if (t == 0) g_off[f] = be[f] - s;
}

// ---------------- transpose dictionary_dec [H,F] -> g_decT [F,H] ----------------
__global__ void transpose_dec_kernel(const float* __restrict__ dec) {
    __shared__ float tile[32][33];
    int bx = blockIdx.x * 32, by = blockIdx.y * 32;
    int f = bx + threadIdx.x, h = by + threadIdx.y;
    #pragma unroll
    for (int i = 0; i < 32; i += 8)
        tile[threadIdx.y + i][threadIdx.x] = dec[(long long)(h + i) * F_ + f];
    __syncthreads();
    int f2 = bx + threadIdx.y, h2 = by + threadIdx.x;
    #pragma unroll
    for (int i = 0; i < 32; i += 8)
        g_decT[(long long)(f2 + i) * H_ + h2] = tile[threadIdx.x][threadIdx.y + i];
}

// ---------------- top-64 on noisy logits + exact fp32 boundary repair + decode + losses ----------------
// g_big holds HMMA logits (bias+relu applied, abs noise < ~1e-5). Features within
// [t-dlo, t+DELTA_] of the 64th value are recomputed with a sequential-k fp32 FMA
// chain + off[f] (bit-identical to the f32x2 GEMM's math), so the selected set
// matches what an exact-fp32 encoder GEMM would select.
__global__ void __launch_bounds__(256) topk_decode_kernel(
    const float* __restrict__ xsrc, const float* __restrict__ enc,
    float* __restrict__ zn, float* __restrict__ xtgt)
{
    int row = blockIdx.x, t = threadIdx.x;
    long long base = (long long)row * H_;
    const float* src = g_big + (long long)row * F_;
    float v[16]; unsigned u[16];
    const float4* s4 = (const float4*)(src + t * 16);
    #pragma unroll
    for (int i = 0; i < 4; i++) {
        float4 q = s4[i];
        v[4*i+0] = q.x; v[4*i+1] = q.y; v[4*i+2] = q.z; v[4*i+3] = q.w;
    }
    #pragma unroll
    for (int i = 0; i < 16; i++) u[i] = (v[i] > 0.f) ? __float_as_uint(v[i]) : 0u;

    // radix-select the 64th-largest value's bits (noisy)
    __shared__ int ish[33];
    unsigned thresh = 0;
    for (int bit = 31; bit >= 0; bit--) {
        unsigned cand = thresh | (1u << bit);
        int c = 0;
        #pragma unroll
        for (int i = 0; i < 16; i++) c += (u[i] >= cand) ? 1 : 0;
        c = blockReduceSumI(c, ish);
        if (c >= TOPK_) thresh = cand;
    }
    float tval = __uint_as_float(thresh);
    float dlo = fminf(DELTA_, 0.25f * tval);

    // classify: definite-in (> t+delta) / band (within [t-dlo, t+delta], positive)
    bool isdef[16], isband[16];
    int def_local = 0, band_local = 0;
    #pragma unroll
    for (int i = 0; i < 16; i++) {
        isdef[i]  = (v[i] > tval + DELTA_);
        isband[i] = (!isdef[i]) && (v[i] >= tval - dlo) && (v[i] > 0.f);
        def_local  += isdef[i]  ? 1 : 0;
        band_local += isband[i] ? 1 : 0;
    }
    __shared__ int sgt[256], sbd[256];
    sgt[t] = def_local; sbd[t] = band_local;
    __syncthreads();
    int def_pre = 0, band_pre = 0, n_def = 0, nb = 0;
    for (int i = 0; i < 256; i++) {
        n_def += sgt[i]; nb += sbd[i];
        if (i < t) { def_pre += sgt[i]; band_pre += sbd[i]; }
    }

    // gather band indices in ascending index order (deterministic)
    __shared__ int   bandIdx[BANDCAP_];
    __shared__ float bandVal[BANDCAP_];
    __shared__ unsigned char bandSel[BANDCAP_];
    {
        int bp = band_pre;
        #pragma unroll
        for (int i = 0; i < 16; i++)
            if (isband[i]) { if (bp < BANDCAP_) bandIdx[bp] = t*16 + i; bp++; }
    }
    if (nb > BANDCAP_) nb = BANDCAP_;

    // stage x_src row
    __shared__ float xs[H_];
    xs[t] = xsrc[base + t];
    xs[t + 256] = xsrc[base + t + 256];
    xs[t + 512] = xsrc[base + t + 512];
    __syncthreads();

    // exact fp32 recompute for band members (sequential k, matches GEMM order)
    for (int b = t; b < nb; b += 256) {
        int f = bandIdx[b];
        const float* er = enc + (long long)f * H_;
        float acc = 0.f;
        #pragma unroll 8
        for (int k = 0; k < H_; k += 4) {
            float4 e4 = *(const float4*)(er + k);
            acc = fmaf(xs[k+0], e4.x, acc);
            acc = fmaf(xs[k+1], e4.y, acc);
            acc = fmaf(xs[k+2], e4.z, acc);
            acc = fmaf(xs[k+3], e4.w, acc);
        }
        bandVal[b] = fmaxf(acc + g_off[f], 0.f);
        bandSel[b] = 0;
    }
    __syncthreads();

    // place definite-ins into selection list
    __shared__ int sidx[TOPK_]; __shared__ float sval[TOPK_];
    {
        int gp = def_pre;
        #pragma unroll
        for (int i = 0; i < 16; i++)
            if (isdef[i]) { sidx[gp] = t*16 + i; sval[gp] = v[i]; gp++; }
    }
    // thread 0: select top-r of band by (exact val desc, idx asc)
    if (t == 0) {
        int r = TOPK_ - n_def;
        if (r < 0) r = 0;
        if (r > nb) r = nb;
        for (int s = 0; s < r; s++) {
            int best = -1; float bv = -1.f;
            for (int b = 0; b < nb; b++) {
                if (bandSel[b]) continue;
                if (bandVal[b] > bv) { bv = bandVal[b]; best = b; }
            }
            bandSel[best] = 1;
            sidx[n_def + s] = bandIdx[best];
            sval[n_def + s] = bandVal[best];
        }
        for (int s = n_def + r; s < TOPK_; s++) { sidx[s] = 0; sval[s] = 0.f; }
    }
    __syncthreads();

    // final per-element values: def keeps noisy v; band keeps exact if selected; else 0
    float w[16];
    {
        int bp = band_pre;
        #pragma unroll
        for (int i = 0; i < 16; i++) {
            float x = 0.f;
            if (isdef[i]) x = v[i];
            else if (isband[i]) {
                if (bp < nb && bandSel[bp]) x = bandVal[bp];
                bp++;
            }
            w[i] = x;
        }
    }
    float4* z4 = (float4*)(zn + (long long)row * F_ + t * 16);
    #pragma unroll
    for (int i = 0; i < 4; i++) z4[i] = make_float4(w[4*i], w[4*i+1], w[4*i+2], w[4*i+3]);

    float rsum = 0.f;
    #pragma unroll
    for (int i = 0; i < 16; i++) rsum += w[i];
    __shared__ float fsh[33];
    float tot = blockReduceSum(rsum, fsh);
    if (t == 0) atomicAdd(&g_acc[2], (double)tot);

    // sparse decode: x_tgt[row,h] = sum_p sval[p] * decT[f_p, h]
    float a0 = 0.f, a1 = 0.f, a2 = 0.f;
    #pragma unroll 4
    for (int p = 0; p < TOPK_; p++) {
        float val = sval[p];
        const float* er = g_decT + (long long)sidx[p] * H_;
        a0 = fmaf(val, er[t],       a0);
        a1 = fmaf(val, er[t + 256], a1);
        a2 = fmaf(val, er[t + 512], a2);
    }
    float s0 = xs[t], s1 = xs[t + 256], s2 = xs[t + 512];
    xtgt[base+t] = a0; xtgt[base+t+256] = a1; xtgt[base+t+512] = a2;
    float d0 = a0 - s0, d1 = a1 - s1, d2 = a2 - s2;
    float ss = blockReduceSum(d0*d0 + d1*d1 + d2*d2, fsh);
    if (t == 0) atomicAdd(&g_acc[1], (double)ss);
}

__global__ void finalize_kernel(float* __restrict__ out) {
    double nh = (double)NROWS_ * (double)H_;
    double ra = g_acc[0] / nh;
    double rc = g_acc[1] / nh;
    double sp = g_acc[2] / ((double)NROWS_ * (double)F_);
    out[0] = (float)(ra + rc + 1e-3 * sp);
    out[1] = (float)rc;
    out[2] = (float)ra;
    out[3] = (float)sp;
}

// ---------------- host ----------------
extern "C" void kernel_launch(void* const* d_in, const int* in_sizes, int n_in,
                              void* d_out, int out_size) {
    const float* zL    = (const float*)d_in[0];
    const float* Wq_l  = (const float*)d_in[1];
    const float* Wk_l  = (const float*)d_in[2];
    const float* Wv_l  = (const float*)d_in[3];
    const float* Wo_l  = (const float*)d_in[4];
    const float* gl    = (const float*)d_in[5];
    const float* bl    = (const float*)d_in[6];
    const float* Wq_d  = (const float*)d_in[7];
    const float* Wk_d  = (const float*)d_in[8];
    const float* Wv_d  = (const float*)d_in[9];
    const float* Wo_d  = (const float*)d_in[10];
    const float* gd    = (const float*)d_in[11];
    const float* bd    = (const float*)d_in[12];
    const float* enc   = (const float*)d_in[13];
    const float* dec   = (const float*)d_in[14];
    const float* bpre  = (const float*)d_in[15];
    const float* benc  = (const float*)d_in[16];
    const float* qtok  = (const float*)d_in[17];

    const long long NHs = (long long)NROWS_ * H_;
    float* out      = (float*)d_out;
    float* o_xprior = out + 4;
    float* o_xtgt   = o_xprior + NHs;
    float* o_xsrc   = o_xtgt + NHs;
    float* o_zn     = o_xsrc + NHs;

    float *px, *pln, *pq, *pk, *pv, *po, *px1, *pbig, *poff;
    cudaGetSymbolAddress((void**)&px,   g_x);
    cudaGetSymbolAddress((void**)&pln,  g_ln);
    cudaGetSymbolAddress((void**)&pq,   g_q);
    cudaGetSymbolAddress((void**)&pk,   g_k);
    cudaGetSymbolAddress((void**)&pv,   g_v);
    cudaGetSymbolAddress((void**)&po,   g_o);
    cudaGetSymbolAddress((void**)&px1,  g_x1);
    cudaGetSymbolAddress((void**)&pbig, g_big);
    cudaGetSymbolAddress((void**)&poff, g_off);

    zero_acc_kernel<<<1, 32>>>();
    build_ln_kernel<<<NROWS_, 256>>>(zL, qtok, gl, bl);

    dim3 gP(H_/128, NROWS_/128);   // 6 x 192
    // L-attention projections (fp32, bit-identical to round 4)
    gemm_kernel<1><<<gP, 128>>>(pln, Wq_l, pq, NROWS_, H_, H_, H_, H_, H_, 1,
                                0,0,0,0,0,0, 1.f, nullptr, nullptr, 0, 0);
    gemm_kernel<1><<<gP, 128>>>(pln, Wk_l, pk, NROWS_, H_, H_, H_, H_, H_, 1,
                                0,0,0,0,0,0, 1.f, nullptr, nullptr, 0, 0);
    gemm_kernel<1><<<gP, 128>>>(pln, Wv_l, pv, NROWS_, H_, H_, H_, H_, H_, 1,
                                0,0,0,0,0,0, 1.f, nullptr, nullptr, 0, 0);
    // scores: per (bd,h): [512,96] x [512,96]^T -> g_big
    float scal = 1.0f / sqrtf((float)HD_);
    dim3 gS(4, 4, BD_ * NHD_);
    gemm_kernel<1><<<gS, 128>>>(pq, pk, pbig, 512, 512, HD_, H_, H_, 512, NHD_,
                                393216LL, 96LL, 393216LL, 96LL, 2097152LL, 262144LL,
                                scal, nullptr, nullptr, 0, 0);
    softmax_kernel<<<BD_ * NHD_ * 512, 128>>>();
    dim3 gPV(1, 4, BD_ * NHD_);
    gemm_kernel<0><<<gPV, 128>>>(pbig, pv, po, 512, HD_, 512, 512, H_, H_, NHD_,
                                 2097152LL, 262144LL, 393216LL, 96LL, 393216LL, 96LL,
                                 1.f, nullptr, nullptr, 0, 0);
    // x1 = x + o @ Wo_l^T
    gemm_kernel<1><<<gP, 128>>>(po, Wo_l, px1, NROWS_, H_, H_, H_, H_, H_, 1,
                                0,0,0,0,0,0, 1.f, nullptr, px, H_, 0);
    // D-attention
    ln_d_kernel<<<NROWS_, 256>>>(gd, bd);
    gemm_kernel<1><<<gP, 128>>>(pln, Wq_d, pq, NROWS_, H_, H_, H_, H_, H_, 1,
                                0,0,0,0,0,0, 1.f, nullptr, nullptr, 0, 0);
    gemm_kernel<1><<<gP, 128>>>(pln, Wk_d, pk, NROWS_, H_, H_, H_, H_, H_, 1,
                                0,0,0,0,0,0, 1.f, nullptr, nullptr, 0, 0);
    gemm_kernel<1><<<gP, 128>>>(pln, Wv_d, pv, NROWS_, H_, H_, H_, H_, H_, 1,
                                0,0,0,0,0,0, 1.f, nullptr, nullptr, 0, 0);
    dattn_kernel<<<B_ * L_ * NHD_, 128>>>();
    // x_prior = x1 + o @ Wo_d^T
    gemm_kernel<1><<<gP, 128>>>(po, Wo_d, o_xprior, NROWS_, H_, H_, H_, H_, H_, 1,
                                0,0,0,0,0,0, 1.f, nullptr, px1, H_, 0);
    xsrc_kernel<<<NROWS_, 256>>>(zL, o_xprior, o_xsrc);
    // SAE encoder: HMMA 3-pass (fast, noisy) — boundary repaired in topk kernel
    off_kernel<<<F_, 128>>>(enc, bpre, benc);
    transpose_dec_kernel<<<dim3(F_/32, H_/32), dim3(32, 8)>>>(dec);
    dim3 gE(F_/128, NROWS_/128);   // 32 x 192
    hgemm3_kernel<<<gE, 256>>>(o_xsrc, enc, pbig, H_, F_, poff, nullptr, 1);
    topk_decode_kernel<<<NROWS_, 256>>>(o_xsrc, enc, o_zn, o_xtgt);
    finalize_kernel<<<1, 1>>>(out);
}

// round 13
// speedup vs baseline: 1.1229x; 1.0354x over previous
#include <cuda_runtime.h>
#include <cuda_fp16.h>
#include <math.h>
#include <stdint.h>

#define B_ 4
#define D_ 12
#define L_ 512
#define H_ 768
#define F_ 4096
#define NHD_ 8
#define HD_ 96
#define TOPK_ 64
#define NROWS_ (B_*D_*L_)            /* 24576 */
#define BD_ (B_*D_)                  /* 48 */
#define DELTA_ 2e-4f
#define BANDCAP_ 512
#define K2_ 1536                     /* hi|lo concatenated K */

// ---------------- static scratch (no allocations allowed) ----------------
__device__ float g_x  [NROWS_*H_];
__device__ float g_ln [NROWS_*H_];
__device__ float g_q  [NROWS_*H_];
__device__ float g_k  [NROWS_*H_];
__device__ float g_v  [NROWS_*H_];
__device__ float g_o  [NROWS_*H_];
__device__ float g_x1 [NROWS_*H_];
__device__ float g_big[100663296];   // scores (384*512*512) then z_dense (24576*4096)
__device__ float g_decT[F_*H_];      // transposed dictionary_dec
__device__ float g_off[F_];
__device__ __half g_xs2 [NROWS_*K2_];  // x_src split: [row][k<768:hi | k>=768:lo]
__device__ __half g_enc2[F_*K2_];      // enc split:   [f][hi|lo]
__device__ double g_acc[3];          // [0]=sum(xprior-zL)^2  [1]=sum(xtgt-xsrc)^2  [2]=sum z

// ---------------- helpers ----------------
__device__ __forceinline__ uint32_t smem_u32(const void* p) {
    uint32_t a;
    asm("{ .reg .u64 t; cvta.to.shared.u64 t, %1; cvt.u32.u64 %0, t; }" : "=r"(a) : "l"(p));
    return a;
}
__device__ __forceinline__ void mma16816(float* c, const uint32_t* a, const uint32_t* b) {
    asm volatile("mma.sync.aligned.m16n8k16.row.col.f32.f16.f16.f32 "
        "{%0,%1,%2,%3}, {%4,%5,%6,%7}, {%8,%9}, {%0,%1,%2,%3};"
        : "+f"(c[0]), "+f"(c[1]), "+f"(c[2]), "+f"(c[3])
        : "r"(a[0]), "r"(a[1]), "r"(a[2]), "r"(a[3]), "r"(b[0]), "r"(b[1]));
}
__device__ __forceinline__ unsigned long long dup_f32x2(float x) {
    unsigned long long r;
    asm("mov.b64 %0, {%1, %1};" : "=l"(r) : "f"(x));
    return r;
}
__device__ __forceinline__ void fma_f32x2(unsigned long long& d,
                                          unsigned long long a, unsigned long long b) {
    asm("fma.rn.f32x2 %0, %1, %2, %0;" : "+l"(d) : "l"(a), "l"(b));
}
__device__ __forceinline__ void unpack_f32x2(float& lo, float& hi, unsigned long long v) {
    asm("mov.b64 {%0, %1}, %2;" : "=f"(lo), "=f"(hi) : "l"(v));
}

// ---------------- reductions ----------------
__device__ __forceinline__ float blockReduceSum(float v, float* sh) {
    int t = threadIdx.x, lane = t & 31, w = t >> 5, nw = blockDim.x >> 5;
    #pragma unroll
    for (int o = 16; o; o >>= 1) v += __shfl_down_sync(0xffffffffu, v, o);
    __syncthreads();
    if (lane == 0) sh[w] = v;
    __syncthreads();
    if (t == 0) { float s = 0.f; for (int i = 0; i < nw; i++) s += sh[i]; sh[32] = s; }
    __syncthreads();
    return sh[32];
}
__device__ __forceinline__ float blockReduceMax(float v, float* sh) {
    int t = threadIdx.x, lane = t & 31, w = t >> 5, nw = blockDim.x >> 5;
    #pragma unroll
    for (int o = 16; o; o >>= 1) v = fmaxf(v, __shfl_down_sync(0xffffffffu, v, o));
    __syncthreads();
    if (lane == 0) sh[w] = v;
    __syncthreads();
    if (t == 0) { float m = sh[0]; for (int i = 1; i < nw; i++) m = fmaxf(m, sh[i]); sh[32] = m; }
    __syncthreads();
    return sh[32];
}
__device__ __forceinline__ int blockReduceSumI(int v, int* sh) {
    int t = threadIdx.x, lane = t & 31, w = t >> 5, nw = blockDim.x >> 5;
    #pragma unroll
    for (int o = 16; o; o >>= 1) v += __shfl_down_sync(0xffffffffu, v, o);
    __syncthreads();
    if (lane == 0) sh[w] = v;
    __syncthreads();
    if (t == 0) { int s = 0; for (int i = 0; i < nw; i++) s += sh[i]; sh[32] = s; }
    __syncthreads();
    return sh[32];
}

// ---------------- misc ----------------
__global__ void zero_acc_kernel() {
    if (threadIdx.x < 3) g_acc[threadIdx.x] = 0.0;
}

__global__ void build_ln_kernel(const float* __restrict__ zL, const float* __restrict__ qtok,
                                const float* __restrict__ gw, const float* __restrict__ bw) {
    int row = blockIdx.x, t = threadIdx.x;
    int l = row % L_, d = (row / L_) % D_, b = row / (L_ * D_);
    const float* src = (d == 0) ? qtok
                                : (zL + ((long long)((b*D_ + (d-1))*L_ + l))*H_);
    float v0 = src[t], v1 = src[t+256], v2 = src[t+512];
    long long base = (long long)row * H_;
    g_x[base+t] = v0; g_x[base+t+256] = v1; g_x[base+t+512] = v2;
    __shared__ float sh[33];
    float mean = blockReduceSum(v0+v1+v2, sh) * (1.0f/H_);
    float d0 = v0-mean, d1 = v1-mean, d2 = v2-mean;
    float var = blockReduceSum(d0*d0+d1*d1+d2*d2, sh) * (1.0f/H_);
    float inv = rsqrtf(var + 1e-5f);
    g_ln[base+t]     = d0*inv*gw[t]     + bw[t];
    g_ln[base+t+256] = d1*inv*gw[t+256] + bw[t+256];
    g_ln[base+t+512] = d2*inv*gw[t+512] + bw[t+512];
}

__global__ void ln_d_kernel(const float* __restrict__ gw, const float* __restrict__ bw) {
    int row = blockIdx.x, t = threadIdx.x;
    long long base = (long long)row * H_;
    float v0 = g_x1[base+t], v1 = g_x1[base+t+256], v2 = g_x1[base+t+512];
    __shared__ float sh[33];
    float mean = blockReduceSum(v0+v1+v2, sh) * (1.0f/H_);
    float d0 = v0-mean, d1 = v1-mean, d2 = v2-mean;
    float var = blockReduceSum(d0*d0+d1*d1+d2*d2, sh) * (1.0f/H_);
    float inv = rsqrtf(var + 1e-5f);
    g_ln[base+t]     = d0*inv*gw[t]     + bw[t];
    g_ln[base+t+256] = d1*inv*gw[t+256] + bw[t+256];
    g_ln[base+t+512] = d2*inv*gw[t+512] + bw[t+512];
}

// ---------------- f32x2 batched SGEMM (all fp32 GEMMs; bit-identical to round 4) ----------------
template<int TRANSB>
__global__ void __launch_bounds__(128) gemm_kernel(
    const float* __restrict__ A, const float* __restrict__ Bm, float* __restrict__ C,
    int M, int Nn, int K, int lda, int ldb, int ldc,
    int zdiv,
    long long sA1, long long sA2, long long sB1, long long sB2,
    long long sC1, long long sC2,
    float alpha, const float* __restrict__ bias,
    const float* __restrict__ res, int ldres, int relu)
{
    __shared__ float As[8][128];
    __shared__ float Bs[8][128];
    int bz = blockIdx.z;
    int z1 = bz / zdiv, z2 = bz - z1 * zdiv;
    A  += z1*sA1 + z2*sA2;
    Bm += z1*sB1 + z2*sB2;
    C  += z1*sC1 + z2*sC2;
    int bm = blockIdx.y * 128, bn = blockIdx.x * 128;
    int t = threadIdx.x;
    int tx = t & 15, ty = t >> 4;

    unsigned long long acc[8][8];
    #pragma unroll
    for (int i = 0; i < 8; i++)
        #pragma unroll
        for (int j = 0; j < 8; j++) acc[i][j] = 0ull;

    int mA = t >> 1;
    int kA = (t & 1) * 4;
    int kB = t >> 4;
    int nB = (t & 15) * 8;

    float4 pa0, pa1, pb0, pb1;
    {
        int gm0 = bm + mA, gm1 = bm + mA + 64;
        pa0 = make_float4(0.f,0.f,0.f,0.f); pa1 = pa0;
        if (gm0 < M) pa0 = *(const float4*)(A + (long long)gm0*lda + kA);
        if (gm1 < M) pa1 = *(const float4*)(A + (long long)gm1*lda + kA);
        if (TRANSB) {
            int gn0 = bn + mA, gn1 = bn + mA + 64;
            pb0 = make_float4(0.f,0.f,0.f,0.f); pb1 = pb0;
            if (gn0 < Nn) pb0 = *(const float4*)(Bm + (long long)gn0*ldb + kA);
            if (gn1 < Nn) pb1 = *(const float4*)(Bm + (long long)gn1*ldb + kA);
        } else {
            const float* bp = Bm + (long long)kB*ldb;
            int gn0 = bn + nB, gn1 = bn + nB + 4;
            pb0 = make_float4(0.f,0.f,0.f,0.f); pb1 = pb0;
            if (gn0 + 3 < Nn) pb0 = *(const float4*)(bp + gn0);
            if (gn1 + 3 < Nn) pb1 = *(const float4*)(bp + gn1);
        }
    }

    for (int k0 = 0; k0 < K; k0 += 8) {
        As[kA+0][mA]    = pa0.x; As[kA+1][mA]    = pa0.y; As[kA+2][mA]    = pa0.z; As[kA+3][mA]    = pa0.w;
        As[kA+0][mA+64] = pa1.x; As[kA+1][mA+64] = pa1.y; As[kA+2][mA+64] = pa1.z; As[kA+3][mA+64] = pa1.w;
        if (TRANSB) {
            Bs[kA+0][mA]    = pb0.x; Bs[kA+1][mA]    = pb0.y; Bs[kA+2][mA]    = pb0.z; Bs[kA+3][mA]    = pb0.w;
            Bs[kA+0][mA+64] = pb1.x; Bs[kA+1][mA+64] = pb1.y; Bs[kA+2][mA+64] = pb1.z; Bs[kA+3][mA+64] = pb1.w;
        } else {
            *(float4*)&Bs[kB][nB]     = pb0;
            *(float4*)&Bs[kB][nB + 4] = pb1;
        }
        __syncthreads();

        int kn = k0 + 8;
        if (kn < K) {
            int gm0 = bm + mA, gm1 = bm + mA + 64;
            pa0 = make_float4(0.f,0.f,0.f,0.f); pa1 = pa0;
            if (gm0 < M) pa0 = *(const float4*)(A + (long long)gm0*lda + (kn + kA));
            if (gm1 < M) pa1 = *(const float4*)(A + (long long)gm1*lda + (kn + kA));
            if (TRANSB) {
                int gn0 = bn + mA, gn1 = bn + mA + 64;
                pb0 = make_float4(0.f,0.f,0.f,0.f); pb1 = pb0;
                if (gn0 < Nn) pb0 = *(const float4*)(Bm + (long long)gn0*ldb + (kn + kA));
                if (gn1 < Nn) pb1 = *(const float4*)(Bm + (long long)gn1*ldb + (kn + kA));
            } else {
                const float* bp = Bm + (long long)(kn + kB)*ldb;
                int gn0 = bn + nB, gn1 = bn + nB + 4;
                pb0 = make_float4(0.f,0.f,0.f,0.f); pb1 = pb0;
                if (gn0 + 3 < Nn) pb0 = *(const float4*)(bp + gn0);
                if (gn1 + 3 < Nn) pb1 = *(const float4*)(bp + gn1);
            }
        }

        #pragma unroll
        for (int kk = 0; kk < 8; kk++) {
            float4 b0 = *(const float4*)&Bs[kk][tx*8];
            float4 b1 = *(const float4*)&Bs[kk][tx*8 + 4];
            unsigned long long bd[8];
            bd[0] = dup_f32x2(b0.x); bd[1] = dup_f32x2(b0.y);
            bd[2] = dup_f32x2(b0.z); bd[3] = dup_f32x2(b0.w);
            bd[4] = dup_f32x2(b1.x); bd[5] = dup_f32x2(b1.y);
            bd[6] = dup_f32x2(b1.z); bd[7] = dup_f32x2(b1.w);
            union { float4 f4[4]; unsigned long long u[8]; } av;
            av.f4[0] = *(const float4*)&As[kk][ty*16];
            av.f4[1] = *(const float4*)&As[kk][ty*16 + 4];
            av.f4[2] = *(const float4*)&As[kk][ty*16 + 8];
            av.f4[3] = *(const float4*)&As[kk][ty*16 + 12];
            #pragma unroll
            for (int ip = 0; ip < 8; ip++)
                #pragma unroll
                for (int j = 0; j < 8; j++)
                    fma_f32x2(acc[ip][j], av.u[ip], bd[j]);
        }
        __syncthreads();
    }

    #pragma unroll
    for (int ip = 0; ip < 8; ip++) {
        float lo[8], hi[8];
        #pragma unroll
        for (int j = 0; j < 8; j++) unpack_f32x2(lo[j], hi[j], acc[ip][j]);
        #pragma unroll
        for (int half = 0; half < 2; half++) {
            int gm = bm + ty*16 + ip*2 + half;
            if (gm >= M) continue;
            const float* vv = half ? hi : lo;
            long long crow = (long long)gm * ldc;
            long long rrow = (long long)gm * ldres;
            #pragma unroll
            for (int j = 0; j < 8; j++) {
                int gn = bn + tx*8 + j;
                if (gn >= Nn) continue;
                float x = vv[j] * alpha;
                if (bias) x += bias[gn];
                if (res)  x += res[rrow + gn];
                if (relu) x = fmaxf(x, 0.f);
                C[crow + gn] = x;
            }
        }
    }
}

// ---------------- optimized HMMA encoder GEMM over pre-split fp16 ----------------
// C[M,4096] = sum over 3 passes of Aseg[M,768] * Bseg[4096,768]^T, +bias, relu.
// A2/B2: [row][1536] = [hi(768) | lo(768)]. grid(F/128, M/128), 256 thr.
__global__ void __launch_bounds__(256) hgemm_enc_kernel(
    const __half* __restrict__ A2, const __half* __restrict__ B2,
    float* __restrict__ C, const float* __restrict__ bias)
{
    __shared__ __half As[128][40];
    __shared__ __half Bs[128][40];
    int t = threadIdx.x, warp = t >> 5, lane = t & 31;
    int g = lane >> 2, tg = lane & 3;
    int wm = warp >> 2, wn = warp & 3;       // 2x4 warp grid; warp tile 64m x 32n
    int bm = blockIdx.y * 128, bn = blockIdx.x * 128;
    int lm = lane >> 3, lr = lane & 7;       // ldmatrix sub-matrix id / row

    float c[4][4][4];
    #pragma unroll
    for (int i = 0; i < 4; i++)
        #pragma unroll
        for (int j = 0; j < 4; j++)
            #pragma unroll
            for (int q = 0; q < 4; q++) c[i][j][q] = 0.f;

    // global chunk map: chunk id c in [0,512): row=c>>2, k8=(c&3)*8. thread loads c=t and c=t+256.
    int ar0 = t >> 2, ak0 = (t & 3) * 8;
    int ar1 = (t + 256) >> 2, ak1 = (t & 3) * 8;   // (t+256)&3 == t&3

    const __half* Arow0 = A2 + (long long)(bm + ar0) * K2_;
    const __half* Arow1 = A2 + (long long)(bm + ar1) * K2_;
    const __half* Brow0 = B2 + (long long)(bn + ar0) * K2_;
    const __half* Brow1 = B2 + (long long)(bn + ar1) * K2_;

    const int NIT = 72;   // 3 passes x 768/32
    uint4 pa0, pa1, pb0, pb1;
    pa0 = *(const uint4*)(Arow0 + ak0);
    pa1 = *(const uint4*)(Arow1 + ak1);
    pb0 = *(const uint4*)(Brow0 + ak0);
    pb1 = *(const uint4*)(Brow1 + ak1);

    for (int it = 0; it < NIT; it++) {
        *(uint4*)&As[ar0][ak0] = pa0;
        *(uint4*)&As[ar1][ak1] = pa1;
        *(uint4*)&Bs[ar0][ak0] = pb0;
        *(uint4*)&Bs[ar1][ak1] = pb1;
        __syncthreads();

        int nx = it + 1;
        if (nx < NIT) {
            int p = nx / 24, kk = (nx - p * 24) * 32;
            int aoff = (p == 1) ? 768 : 0;
            int boff = (p == 2) ? 768 : 0;
            pa0 = *(const uint4*)(Arow0 + aoff + kk + ak0);
            pa1 = *(const uint4*)(Arow1 + aoff + kk + ak1);
            pb0 = *(const uint4*)(Brow0 + boff + kk + ak0);
            pb1 = *(const uint4*)(Brow1 + boff + kk + ak1);
        }

        #pragma unroll
        for (int s = 0; s < 2; s++) {
            uint32_t af[4][4];
            #pragma unroll
            for (int mt = 0; mt < 4; mt++) {
                int row = wm * 64 + mt * 16 + (lm & 1) * 8 + lr;
                int kc = s * 16 + (lm >> 1) * 8;
                uint32_t addr = smem_u32(&As[row][kc]);
                asm volatile("ldmatrix.sync.aligned.m8n8.x4.shared.b16 {%0,%1,%2,%3}, [%4];"
                    : "=r"(af[mt][0]), "=r"(af[mt][1]), "=r"(af[mt][2]), "=r"(af[mt][3])
                    : "r"(addr));
            }
            uint32_t bf[4][2];
            #pragma unroll
            for (int q = 0; q < 2; q++) {
                int n = wn * 32 + q * 16 + (lm >> 1) * 8 + lr;
                int kc = s * 16 + (lm & 1) * 8;
                uint32_t addr = smem_u32(&Bs[n][kc]);
                uint32_t r0, r1, r2, r3;
                asm volatile("ldmatrix.sync.aligned.m8n8.x4.shared.b16 {%0,%1,%2,%3}, [%4];"
                    : "=r"(r0), "=r"(r1), "=r"(r2), "=r"(r3) : "r"(addr));
                bf[q*2][0]   = r0; bf[q*2][1]   = r1;
                bf[q*2+1][0] = r2; bf[q*2+1][1] = r3;
            }
            #pragma unroll
            for (int mt = 0; mt < 4; mt++)
                #pragma unroll
                for (int nt = 0; nt < 4; nt++)
                    mma16816(c[mt][nt], af[mt], bf[nt]);
        }
        __syncthreads();
    }

    // epilogue: +bias, relu
    #pragma unroll
    for (int mt = 0; mt < 4; mt++) {
        #pragma unroll
        for (int hf = 0; hf < 2; hf++) {
            int m = bm + wm * 64 + mt * 16 + g + hf * 8;
            long long crow = (long long)m * F_;
            #pragma unroll
            for (int nt = 0; nt < 4; nt++) {
                int n = bn + wn * 32 + nt * 8 + 2 * tg;
                float vx = c[mt][nt][hf * 2 + 0] + bias[n];
                float vy = c[mt][nt][hf * 2 + 1] + bias[n + 1];
                vx = fmaxf(vx, 0.f); vy = fmaxf(vy, 0.f);
                float2 o2; o2.x = vx; o2.y = vy;
                *(float2*)(C + crow + n) = o2;
            }
        }
    }
}

// ---------------- softmax over rows of 512 ----------------
__global__ void softmax_kernel() {
    float* p = g_big + (long long)blockIdx.x * 512;
    int t = threadIdx.x; // 128
    float4 v = ((float4*)p)[t];
    __shared__ float sh[33];
    float m = blockReduceMax(fmaxf(fmaxf(v.x, v.y), fmaxf(v.z, v.w)), sh);
    v.x = expf(v.x - m); v.y = expf(v.y - m); v.z = expf(v.z - m); v.w = expf(v.w - m);
    float s = blockReduceSum(v.x + v.y + v.z + v.w, sh);
    float inv = 1.0f / s;
    v.x *= inv; v.y *= inv; v.z *= inv; v.w *= inv;
    ((float4*)p)[t] = v;
}

// ---------------- causal attention over D (seq len 12) ----------------
__global__ void dattn_kernel() {
    int bid = blockIdx.x;
    int h = bid % NHD_;
    int l = (bid / NHD_) % L_;
    int b = bid / (NHD_ * L_);
    __shared__ float sq[D_][HD_], sk[D_][HD_], sv[D_][HD_];
    __shared__ float sp[D_][D_];
    int t = threadIdx.x; // 128
    for (int idx = t; idx < D_*HD_; idx += 128) {
        int d = idx / HD_, c = idx - d*HD_;
        long long g = ((long long)((b*D_ + d)*L_ + l))*H_ + h*HD_ + c;
        sq[d][c] = g_q[g]; sk[d][c] = g_k[g]; sv[d][c] = g_v[g];
    }
    __syncthreads();
    const float scale = rsqrtf((float)HD_);
    for (int idx = t; idx < D_*D_; idx += 128) {
        int i = idx / D_, j = idx - i*D_;
        float s = 0.f;
        if (j <= i) {
            #pragma unroll 8
            for (int c = 0; c < HD_; c++) s = fmaf(sq[i][c], sk[j][c], s);
            s *= scale;
        }
        sp[i][j] = s;
    }
    __syncthreads();
    if (t < D_) {
        int i = t;
        float m = -1e30f;
        for (int j = 0; j <= i; j++) m = fmaxf(m, sp[i][j]);
        float sum = 0.f;
        for (int j = 0; j <= i; j++) { float e = expf(sp[i][j] - m); sp[i][j] = e; sum += e; }
        float inv = 1.0f / sum;
        for (int j = 0; j <= i; j++) sp[i][j] *= inv;
        for (int j = i + 1; j < D_; j++) sp[i][j] = 0.f;
    }
    __syncthreads();
    for (int idx = t; idx < D_*HD_; idx += 128) {
        int i = idx / HD_, c = idx - i*HD_;
        float acc = 0.f;
        for (int j = 0; j <= i; j++) acc = fmaf(sp[i][j], sv[j][c], acc);
        g_o[((long long)((b*D_ + i)*L_ + l))*H_ + h*HD_ + c] = acc;
    }
}

// ---------------- x_src = zL - x_prior (+ fused fp16 hi/lo split) ----------------
__global__ void xsrc_kernel(const float* __restrict__ zL, const float* __restrict__ xp,
                            float* __restrict__ xs) {
    int row = blockIdx.x, t = threadIdx.x;
    long long base = (long long)row * H_ + t;
    long long b2 = (long long)row * K2_ + t;
    float d0 = zL[base]     - xp[base];
    float d1 = zL[base+256] - xp[base+256];
    float d2 = zL[base+512] - xp[base+512];
    xs[base] = d0; xs[base+256] = d1; xs[base+512] = d2;
    __half h0 = __float2half_rn(d0), h1 = __float2half_rn(d1), h2 = __float2half_rn(d2);
    g_xs2[b2]       = h0; g_xs2[b2+256]     = h1; g_xs2[b2+512]     = h2;
    g_xs2[b2+768]   = __float2half_rn(d0 - __half2float(h0));
    g_xs2[b2+1024]  = __float2half_rn(d1 - __half2float(h1));
    g_xs2[b2+1280]  = __float2half_rn(d2 - __half2float(h2));
    __shared__ float sh[33];
    float s = blockReduceSum(d0*d0 + d1*d1 + d2*d2, sh);
    if (threadIdx.x == 0) atomicAdd(&g_acc[0], (double)s);
}

// ---------------- enc split: [F,H] fp32 -> [F][hi|lo] fp16 ----------------
__global__ void enc_split_kernel(const float* __restrict__ enc) {
    int f = blockIdx.x, t = threadIdx.x;
    long long base = (long long)f * H_ + t;
    long long b2 = (long long)f * K2_ + t;
    #pragma unroll
    for (int j = 0; j < 3; j++) {
        float v = enc[base + j*256];
        __half h = __float2half_rn(v);
        g_enc2[b2 + j*256] = h;
        g_enc2[b2 + 768 + j*256] = __float2half_rn(v - __half2float(h));
    }
}

// ---------------- off[f] = bias_enc[f] - dot(bias_pre, enc[f,:]) ----------------
__global__ void off_kernel(const float* __restrict__ enc, const float* __restrict__ bp,
                           const float* __restrict__ be) {
    int f = blockIdx.x, t = threadIdx.x; // 128
    const float* er = enc + (long long)f * H_;
    float s = 0.f;
    for (int c = t; c < H_; c += 128) s = fmaf(bp[c], er[c], s);
    __shared__ float sh[33];
    s = blockReduceSum(s, sh);
    if (t == 0) g_off[f] = be[f] - s;
}

// ---------------- transpose dictionary_dec [H,F] -> g_decT [F,H] ----------------
__global__ void transpose_dec_kernel(const float* __restrict__ dec) {
    __shared__ float tile[32][33];
    int bx = blockIdx.x * 32, by = blockIdx.y * 32;
    int f = bx + threadIdx.x, h = by + threadIdx.y;
    #pragma unroll
    for (int i = 0; i < 32; i += 8)
        tile[threadIdx.y + i][threadIdx.x] = dec[(long long)(h + i) * F_ + f];
    __syncthreads();
    int f2 = bx + threadIdx.y, h2 = by + threadIdx.x;
    #pragma unroll
    for (int i = 0; i < 32; i += 8)
        g_decT[(long long)(f2 + i) * H_ + h2] = tile[threadIdx.x][threadIdx.y + i];
}

// ---------------- top-64 on noisy logits + exact fp32 boundary repair + decode + losses ----------------
__global__ void __launch_bounds__(256) topk_decode_kernel(
    const float* __restrict__ xsrc, const float* __restrict__ enc,
    float* __restrict__ zn, float* __restrict__ xtgt)
{
    int row = blockIdx.x, t = threadIdx.x;
    long long base = (long long)row * H_;
    const float* src = g_big + (long long)row * F_;
    float v[16]; unsigned u[16];
    const float4* s4 = (const float4*)(src + t * 16);
    #pragma unroll
    for (int i = 0; i < 4; i++) {
        float4 q = s4[i];
        v[4*i+0] = q.x; v[4*i+1] = q.y; v[4*i+2] = q.z; v[4*i+3] = q.w;
    }
    #pragma unroll
    for (int i = 0; i < 16; i++) u[i] = (v[i] > 0.f) ? __float_as_uint(v[i]) : 0u;

    // radix-select the 64th-largest value's bits (noisy)
    __shared__ int ish[33];
    unsigned thresh = 0;
    for (int bit = 31; bit >= 0; bit--) {
        unsigned cand = thresh | (1u << bit);
        int c = 0;
        #pragma unroll
        for (int i = 0; i < 16; i++) c += (u[i] >= cand) ? 1 : 0;
        c = blockReduceSumI(c, ish);
        if (c >= TOPK_) thresh = cand;
    }
    float tval = __uint_as_float(thresh);
    float dlo = fminf(DELTA_, 0.25f * tval);

    bool isdef[16], isband[16];
    int def_local = 0, band_local = 0;
    #pragma unroll
    for (int i = 0; i < 16; i++) {
        isdef[i]  = (v[i] > tval + DELTA_);
        isband[i] = (!isdef[i]) && (v[i] >= tval - dlo) && (v[i] > 0.f);
        def_local  += isdef[i]  ? 1 : 0;
        band_local += isband[i] ? 1 : 0;
    }
    __shared__ int sgt[256], sbd[256];
    sgt[t] = def_local; sbd[t] = band_local;
    __syncthreads();
    int def_pre = 0, band_pre = 0, n_def = 0, nb = 0;
    for (int i = 0; i < 256; i++) {
        n_def += sgt[i]; nb += sbd[i];
        if (i < t) { def_pre += sgt[i]; band_pre += sbd[i]; }
    }

    __shared__ int   bandIdx[BANDCAP_];
    __shared__ float bandVal[BANDCAP_];
    __shared__ unsigned char bandSel[BANDCAP_];
    {
        int bp = band_pre;
        #pragma unroll
        for (int i = 0; i < 16; i++)
            if (isband[i]) { if (bp < BANDCAP_) bandIdx[bp] = t*16 + i; bp++; }
    }
    if (nb > BANDCAP_) nb = BANDCAP_;

    __shared__ float xs[H_];
    xs[t] = xsrc[base + t];
    xs[t + 256] = xsrc[base + t + 256];
    xs[t + 512] = xsrc[base + t + 512];
    __syncthreads();

    for (int b = t; b < nb; b += 256) {
        int f = bandIdx[b];
        const float* er = enc + (long long)f * H_;
        float acc = 0.f;
        #pragma unroll 8
        for (int k = 0; k < H_; k += 4) {
            float4 e4 = *(const float4*)(er + k);
            acc = fmaf(xs[k+0], e4.x, acc);
            acc = fmaf(xs[k+1], e4.y, acc);
            acc = fmaf(xs[k+2], e4.z, acc);
            acc = fmaf(xs[k+3], e4.w, acc);
        }
        bandVal[b] = fmaxf(acc + g_off[f], 0.f);
        bandSel[b] = 0;
    }
    __syncthreads();

    __shared__ int sidx[TOPK_]; __shared__ float sval[TOPK_];
    {
        int gp = def_pre;
        #pragma unroll
        for (int i = 0; i < 16; i++)
            if (isdef[i]) { sidx[gp] = t*16 + i; sval[gp] = v[i]; gp++; }
    }
    if (t == 0) {
        int r = TOPK_ - n_def;
        if (r < 0) r = 0;
        if (r > nb) r = nb;
        for (int s = 0; s < r; s++) {
            int best = -1; float bv = -1.f;
            for (int b = 0; b < nb; b++) {
                if (bandSel[b]) continue;
                if (bandVal[b] > bv) { bv = bandVal[b]; best = b; }
            }
            bandSel[best] = 1;
            sidx[n_def + s] = bandIdx[best];
            sval[n_def + s] = bandVal[best];
        }
        for (int s = n_def + r; s < TOPK_; s++) { sidx[s] = 0; sval[s] = 0.f; }
    }
    __syncthreads();

    float w[16];
    {
        int bp = band_pre;
        #pragma unroll
        for (int i = 0; i < 16; i++) {
            float x = 0.f;
            if (isdef[i]) x = v[i];
            else if (isband[i]) {
                if (bp < nb && bandSel[bp]) x = bandVal[bp];
                bp++;
            }
            w[i] = x;
        }
    }
    float4* z4 = (float4*)(zn + (long long)row * F_ + t * 16);
    #pragma unroll
    for (int i = 0; i < 4; i++) z4[i] = make_float4(w[4*i], w[4*i+1], w[4*i+2], w[4*i+3]);

    float rsum = 0.f;
    #pragma unroll
    for (int i = 0; i < 16; i++) rsum += w[i];
    __shared__ float fsh[33];
    float tot = blockReduceSum(rsum, fsh);
    if (t == 0) atomicAdd(&g_acc[2], (double)tot);

    float a0 = 0.f, a1 = 0.f, a2 = 0.f;
    #pragma unroll 4
    for (int p = 0; p < TOPK_; p++) {
        float val = sval[p];
        const float* er = g_decT + (long long)sidx[p] * H_;
        a0 = fmaf(val, er[t],       a0);
        a1 = fmaf(val, er[t + 256], a1);
        a2 = fmaf(val, er[t + 512], a2);
    }
    float s0 = xs[t], s1 = xs[t + 256], s2 = xs[t + 512];
    xtgt[base+t] = a0; xtgt[base+t+256] = a1; xtgt[base+t+512] = a2;
    float d0 = a0 - s0, d1 = a1 - s1, d2 = a2 - s2;
    float ss = blockReduceSum(d0*d0 + d1*d1 + d2*d2, fsh);
    if (t == 0) atomicAdd(&g_acc[1], (double)ss);
}

__global__ void finalize_kernel(float* __restrict__ out) {
    double nh = (double)NROWS_ * (double)H_;
    double ra = g_acc[0] / nh;
    double rc = g_acc[1] / nh;
    double sp = g_acc[2] / ((double)NROWS_ * (double)F_);
    out[0] = (float)(ra + rc + 1e-3 * sp);
    out[1] = (float)rc;
    out[2] = (float)ra;
    out[3] = (float)sp;
}

// ---------------- host ----------------
extern "C" void kernel_launch(void* const* d_in, const int* in_sizes, int n_in,
                              void* d_out, int out_size) {
    const float* zL    = (const float*)d_in[0];
    const float* Wq_l  = (const float*)d_in[1];
    const float* Wk_l  = (const float*)d_in[2];
    const float* Wv_l  = (const float*)d_in[3];
    const float* Wo_l  = (const float*)d_in[4];
    const float* gl    = (const float*)d_in[5];
    const float* bl    = (const float*)d_in[6];
    const float* Wq_d  = (const float*)d_in[7];
    const float* Wk_d  = (const float*)d_in[8];
    const float* Wv_d  = (const float*)d_in[9];
    const float* Wo_d  = (const float*)d_in[10];
    const float* gd    = (const float*)d_in[11];
    const float* bd    = (const float*)d_in[12];
    const float* enc   = (const float*)d_in[13];
    const float* dec   = (const float*)d_in[14];
    const float* bpre  = (const float*)d_in[15];
    const float* benc  = (const float*)d_in[16];
    const float* qtok  = (const float*)d_in[17];

    const long long NHs = (long long)NROWS_ * H_;
    float* out      = (float*)d_out;
    float* o_xprior = out + 4;
    float* o_xtgt   = o_xprior + NHs;
    float* o_xsrc   = o_xtgt + NHs;
    float* o_zn     = o_xsrc + NHs;

    float *px, *pln, *pq, *pk, *pv, *po, *px1, *pbig, *poff;
    __half *pxs2, *penc2;
    cudaGetSymbolAddress((void**)&px,   g_x);
    cudaGetSymbolAddress((void**)&pln,  g_ln);
    cudaGetSymbolAddress((void**)&pq,   g_q);
    cudaGetSymbolAddress((void**)&pk,   g_k);
    cudaGetSymbolAddress((void**)&pv,   g_v);
    cudaGetSymbolAddress((void**)&po,   g_o);
    cudaGetSymbolAddress((void**)&px1,  g_x1);
    cudaGetSymbolAddress((void**)&pbig, g_big);
    cudaGetSymbolAddress((void**)&poff, g_off);
    cudaGetSymbolAddress((void**)&pxs2, g_xs2);
    cudaGetSymbolAddress((void**)&penc2, g_enc2);

    zero_acc_kernel<<<1, 32>>>();
    build_ln_kernel<<<NROWS_, 256>>>(zL, qtok, gl, bl);
    // independent prep (overlaps nothing but cheap)
    enc_split_kernel<<<F_, 256>>>(enc);
    off_kernel<<<F_, 128>>>(enc, bpre, benc);
    transpose_dec_kernel<<<dim3(F_/32, H_/32), dim3(32, 8)>>>(dec);

    dim3 gP(H_/128, NROWS_/128);   // 6 x 192
    gemm_kernel<1><<<gP, 128>>>(pln, Wq_l, pq, NROWS_, H_, H_, H_, H_, H_, 1,
                                0,0,0,0,0,0, 1.f, nullptr, nullptr, 0, 0);
    gemm_kernel<1><<<gP, 128>>>(pln, Wk_l, pk, NROWS_, H_, H_, H_, H_, H_, 1,
                                0,0,0,0,0,0, 1.f, nullptr, nullptr, 0, 0);
    gemm_kernel<1><<<gP, 128>>>(pln, Wv_l, pv, NROWS_, H_, H_, H_, H_, H_, 1,
                                0,0,0,0,0,0, 1.f, nullptr, nullptr, 0, 0);
    float scal = 1.0f / sqrtf((float)HD_);
    dim3 gS(4, 4, BD_ * NHD_);
    gemm_kernel<1><<<gS, 128>>>(pq, pk, pbig, 512, 512, HD_, H_, H_, 512, NHD_,
                                393216LL, 96LL, 393216LL, 96LL, 2097152LL, 262144LL,
                                scal, nullptr, nullptr, 0, 0);
    softmax_kernel<<<BD_ * NHD_ * 512, 128>>>();
    dim3 gPV(1, 4, BD_ * NHD_);
    gemm_kernel<0><<<gPV, 128>>>(pbig, pv, po, 512, HD_, 512, 512, H_, H_, NHD_,
                                 2097152LL, 262144LL, 393216LL, 96LL, 393216LL, 96LL,
                                 1.f, nullptr, nullptr, 0, 0);
    gemm_kernel<1><<<gP, 128>>>(po, Wo_l, px1, NROWS_, H_, H_, H_, H_, H_, 1,
                                0,0,0,0,0,0, 1.f, nullptr, px, H_, 0);
    ln_d_kernel<<<NROWS_, 256>>>(gd, bd);
    gemm_kernel<1><<<gP, 128>>>(pln, Wq_d, pq, NROWS_, H_, H_, H_, H_, H_, 1,
                                0,0,0,0,0,0, 1.f, nullptr, nullptr, 0, 0);
    gemm_kernel<1><<<gP, 128>>>(pln, Wk_d, pk, NROWS_, H_, H_, H_, H_, H_, 1,
                                0,0,0,0,0,0, 1.f, nullptr, nullptr, 0, 0);
    gemm_kernel<1><<<gP, 128>>>(pln, Wv_d, pv, NROWS_, H_, H_, H_, H_, H_, 1,
                                0,0,0,0,0,0, 1.f, nullptr, nullptr, 0, 0);
    dattn_kernel<<<B_ * L_ * NHD_, 128>>>();
    gemm_kernel<1><<<gP, 128>>>(po, Wo_d, o_xprior, NROWS_, H_, H_, H_, H_, H_, 1,
                                0,0,0,0,0,0, 1.f, nullptr, px1, H_, 0);
    xsrc_kernel<<<NROWS_, 256>>>(zL, o_xprior, o_xsrc);
    // SAE encoder: optimized HMMA over pre-split fp16
    dim3 gE(F_/128, NROWS_/128);   // 32 x 192
    hgemm_enc_kernel<<<gE, 256>>>(pxs2, penc2, pbig, poff);
    topk_decode_kernel<<<NROWS_, 256>>>(o_xsrc, enc, o_zn, o_xtgt);
    finalize_kernel<<<1, 1>>>(out);
}